// round 8
// baseline (speedup 1.0000x reference)
#include <cuda_runtime.h>
#include <cstdint>

#define NB   4
#define SEQ  2048
#define NH   16
#define DEP  64
#define DM   1024
#define MROWS (NB*SEQ)

typedef unsigned short u16;
typedef unsigned int   u32;

__device__ u16 g_ah [(size_t)MROWS*DM];
__device__ u16 g_al [(size_t)MROWS*DM];
__device__ u16 g_w_h[4][(size_t)DM*DM];
__device__ u16 g_w_l[4][(size_t)DM*DM];
__device__ u16 g_qhh[(size_t)MROWS*DM];
__device__ u16 g_qhl[(size_t)MROWS*DM];
__device__ u16 g_khh[(size_t)MROWS*DM];
__device__ u16 g_khl[(size_t)MROWS*DM];
__device__ u16 g_vhh[(size_t)MROWS*DM];
__device__ u16 g_vhl[(size_t)MROWS*DM];
__device__ u16 g_ch [(size_t)MROWS*DM];
__device__ u16 g_cl [(size_t)MROWS*DM];
__device__ float g_opart[2][(size_t)MROWS*DM];
__device__ float g_lpart[2][(size_t)NB*NH*SEQ];

__device__ __forceinline__ unsigned smem_u32(const void* p) {
    unsigned r;
    asm("{ .reg .u64 t; cvta.to.shared.u64 t, %1; cvt.u32.u64 %0, t; }"
        : "=r"(r) : "l"(p));
    return r;
}

__device__ __forceinline__ void ldsm4(u32& r0, u32& r1, u32& r2, u32& r3,
                                      unsigned addr) {
    asm volatile("ldmatrix.sync.aligned.m8n8.x4.shared.b16 {%0,%1,%2,%3}, [%4];"
                 : "=r"(r0), "=r"(r1), "=r"(r2), "=r"(r3) : "r"(addr));
}
__device__ __forceinline__ void ldsm4t(u32& r0, u32& r1, u32& r2, u32& r3,
                                       unsigned addr) {
    asm volatile("ldmatrix.sync.aligned.m8n8.x4.trans.shared.b16 {%0,%1,%2,%3}, [%4];"
                 : "=r"(r0), "=r"(r1), "=r"(r2), "=r"(r3) : "r"(addr));
}
__device__ __forceinline__ void mma16816(float* d, const u32* a, const u32* b) {
    asm volatile("mma.sync.aligned.m16n8k16.row.col.f32.bf16.bf16.f32 "
                 "{%0,%1,%2,%3}, {%4,%5,%6,%7}, {%8,%9}, {%0,%1,%2,%3};"
                 : "+f"(d[0]), "+f"(d[1]), "+f"(d[2]), "+f"(d[3])
                 : "r"(a[0]), "r"(a[1]), "r"(a[2]), "r"(a[3]),
                   "r"(b[0]), "r"(b[1]));
}

#define CP_ASYNC16(dst, src) \
    asm volatile("cp.async.cg.shared.global [%0], [%1], 16;" :: "r"(dst), "l"(src))
#define CP_COMMIT() asm volatile("cp.async.commit_group;" ::: "memory")
#define CP_WAIT0()  asm volatile("cp.async.wait_group 0;" ::: "memory")

__device__ __forceinline__ float fexp(float x) {
    float z  = fmaxf(x * 1.4426950408889634f, -126.0f);
    float zi = z + 12582912.0f;
    int   n  = __float_as_int(zi);
    float f  = zi - 12582912.0f;
    float r  = z - f;
    float p  = 0.0013333558f;
    p = fmaf(p, r, 0.0096181291f);
    p = fmaf(p, r, 0.0555041087f);
    p = fmaf(p, r, 0.2402265069f);
    p = fmaf(p, r, 0.6931471806f);
    p = fmaf(p, r, 1.0f);
    int bits = __float_as_int(p) + (int)((unsigned)n << 23);
    return __int_as_float(bits);
}

__device__ __forceinline__ void split4(float4 v, uint2& hi, uint2& lo) {
    unsigned b0 = __float_as_uint(v.x), b1 = __float_as_uint(v.y);
    unsigned b2 = __float_as_uint(v.z), b3 = __float_as_uint(v.w);
    hi.x = __byte_perm(b0, b1, 0x7632);
    hi.y = __byte_perm(b2, b3, 0x7632);
    float r0 = v.x - __uint_as_float(b0 & 0xffff0000u);
    float r1 = v.y - __uint_as_float(b1 & 0xffff0000u);
    float r2 = v.z - __uint_as_float(b2 & 0xffff0000u);
    float r3 = v.w - __uint_as_float(b3 & 0xffff0000u);
    lo.x = __byte_perm(__float_as_uint(r0), __float_as_uint(r1), 0x7632);
    lo.y = __byte_perm(__float_as_uint(r2), __float_as_uint(r3), 0x7632);
}

__device__ __forceinline__ u32 packbf(float a, float b) {
    return __byte_perm(__float_as_uint(a), __float_as_uint(b), 0x7632);
}
__device__ __forceinline__ float truncbf(float a) {
    return __uint_as_float(__float_as_uint(a) & 0xffff0000u);
}

__global__ void conv_split(const float4* __restrict__ src,
                           uint2* __restrict__ hi, uint2* __restrict__ lo, int n4)
{
    int i = blockIdx.x * blockDim.x + threadIdx.x;
    if (i >= n4) return;
    float4 v = src[i];
    uint2 h, l;
    split4(v, h, l);
    hi[i] = h; lo[i] = l;
}

__global__ void merge_ctx(const float4* __restrict__ O0,
                          const float4* __restrict__ O1,
                          const float* __restrict__ L0,
                          const float* __restrict__ L1,
                          u16* __restrict__ Ch, u16* __restrict__ Cl)
{
    int i = blockIdx.x * blockDim.x + threadIdx.x;
    int row = i >> 4;
    int d4  = (i & 15) << 2;
    float inv = 1.f / (L0[row] + L1[row]);
    float4 a = O0[i], c = O1[i];
    float x0 = (a.x + c.x) * inv, x1 = (a.y + c.y) * inv;
    float x2 = (a.z + c.z) * inv, x3 = (a.w + c.w) * inv;
    float h0 = truncbf(x0), h1 = truncbf(x1), h2 = truncbf(x2), h3 = truncbf(x3);
    int bh = row >> 11, s = row & (SEQ - 1);
    int b = bh >> 4, h = bh & 15;
    size_t ob = ((size_t)(b*SEQ + s) * DM) + h*64 + d4;
    *(uint2*)(Ch + ob) = make_uint2(packbf(h0, h1), packbf(h2, h3));
    *(uint2*)(Cl + ob) = make_uint2(packbf(x0 - h0, x1 - h1),
                                    packbf(x2 - h2, x3 - h3));
}

#define GP 40
#define STAGE_B 40960
#define GSMEM_BYTES (2*STAGE_B)

#define GEMM_ISSUE(chunk, stage) do { \
    unsigned _db = sbase + (stage)*STAGE_B; \
    int _ck = (chunk) * 32; \
    _Pragma("unroll") \
    for (int _i = 0; _i < 8; _i++) { \
        int _pl = _i >> 1; \
        int _row = ((_i & 1) << 6) + trow; \
        const u16* _s = srcs[_pl] + (size_t)_row * DM + _ck + tc16 * 8; \
        unsigned _d = _db + _pl * 10240 + _row * 80 + tc16 * 16; \
        CP_ASYNC16(_d, _s); \
    } \
    CP_COMMIT(); \
} while (0)

__global__ void __launch_bounds__(256, 2) gemm_mma2(
    const u16* __restrict__ Ah, const u16* __restrict__ Al,
    const u16* __restrict__ Wh, const u16* __restrict__ Wl,
    const float* __restrict__ bias,
    float* __restrict__ Cf, u16* __restrict__ Ch, u16* __restrict__ Cl,
    int mode, float scale)
{
    extern __shared__ char gsm[];
    const unsigned sbase = smem_u32(gsm);
    const int tid  = threadIdx.x;
    const int lane = tid & 31;
    const int warp = tid >> 5;
    const int warp_m = warp & 1, warp_n = warp >> 1;
    const int bn = blockIdx.x, bm = blockIdx.y;

    const u16* srcs[4];
    srcs[0] = Ah + (size_t)(bm * 128) * DM;
    srcs[1] = Al + (size_t)(bm * 128) * DM;
    srcs[2] = Wh + (size_t)(bn * 128) * DM;
    srcs[3] = Wl + (size_t)(bn * 128) * DM;

    const int trow = tid >> 2;
    const int tc16 = tid & 3;

    float acc[4][4][4];
#pragma unroll
    for (int i = 0; i < 4; i++)
#pragma unroll
        for (int j = 0; j < 4; j++)
#pragma unroll
            for (int t = 0; t < 4; t++) acc[i][j][t] = 0.f;

    const unsigned OFF_AH = 0, OFF_AL = 10240, OFF_WH = 20480, OFF_WL = 30720;
    const unsigned a_row = warp_m*64 + (lane & 15);
    const unsigned a_kof = (lane >> 4) * 8;
    const unsigned b_row = warp_n*32 + (lane & 7) + ((lane & 16) >> 1);
    const unsigned b_kof = (lane & 8);

    GEMM_ISSUE(0, 0);

    const int NCHUNK = DM / 32;
    for (int c = 0; c < NCHUNK; c++) {
        CP_WAIT0();
        __syncthreads();
        if (c + 1 < NCHUNK) GEMM_ISSUE(c + 1, (c + 1) & 1);

        const unsigned st = sbase + (unsigned)(c & 1) * STAGE_B;
#pragma unroll
        for (int ks = 0; ks < 2; ks++) {
            const unsigned kbyte = (unsigned)(ks * 16) * 2;
            u32 bh[8], bl[8];
#pragma unroll
            for (int jp = 0; jp < 2; jp++) {
                unsigned roff = (b_row + jp*16) * (GP*2) + kbyte + b_kof*2;
                ldsm4(bh[jp*4+0], bh[jp*4+1], bh[jp*4+2], bh[jp*4+3],
                      st + OFF_WH + roff);
                ldsm4(bl[jp*4+0], bl[jp*4+1], bl[jp*4+2], bl[jp*4+3],
                      st + OFF_WL + roff);
            }
#pragma unroll
            for (int i = 0; i < 4; i++) {
                unsigned roff = (a_row + i*16) * (GP*2) + kbyte + a_kof*2;
                u32 ah[4], al[4];
                ldsm4(ah[0], ah[1], ah[2], ah[3], st + OFF_AH + roff);
                ldsm4(al[0], al[1], al[2], al[3], st + OFF_AL + roff);
#pragma unroll
                for (int j = 0; j < 4; j++) {
                    mma16816(acc[i][j], ah, &bh[j*2]);
                    mma16816(acc[i][j], ah, &bl[j*2]);
                    mma16816(acc[i][j], al, &bh[j*2]);
                }
            }
        }
        __syncthreads();
    }

    const int gid = lane >> 2, tig = lane & 3;
#pragma unroll
    for (int i = 0; i < 4; i++) {
#pragma unroll
        for (int j = 0; j < 4; j++) {
            int gnc = bn*128 + warp_n*32 + j*8 + tig*2;
            float2 bv = *(const float2*)(bias + gnc);
#pragma unroll
            for (int half = 0; half < 2; half++) {
                int m = bm*128 + warp_m*64 + i*16 + gid + half*8;
                float o0 = (acc[i][j][half*2+0] + bv.x) * scale;
                float o1 = (acc[i][j][half*2+1] + bv.y) * scale;
                if (mode == 0) {
                    *(float2*)(Cf + (size_t)m * DM + gnc) = make_float2(o0, o1);
                } else {
                    int bi = m >> 11, s = m & (SEQ - 1);
                    int hh = gnc >> 6, d = gnc & 63;
                    size_t idx = (((size_t)(bi*NH + hh) * SEQ + s) << 6) + d;
                    float h0 = truncbf(o0), h1 = truncbf(o1);
                    *(u32*)(Ch + idx) = packbf(h0, h1);
                    *(u32*)(Cl + idx) = packbf(o0 - h0, o1 - h1);
                }
            }
        }
    }
}

#define AQH 0
#define AQL 18432
#define ABUF0 36864
#define ABUF1 73728
#define ASMEM_BYTES 110592
#define NKT (SEQ/64/2)

__global__ void __launch_bounds__(256, 2) attn_mma_kernel(
    const u16* __restrict__ Qhh, const u16* __restrict__ Qhl,
    const u16* __restrict__ Khh, const u16* __restrict__ Khl,
    const u16* __restrict__ Vhh, const u16* __restrict__ Vhl,
    float* __restrict__ Opart, float* __restrict__ Lpart)
{
    extern __shared__ char asm_[];
    const unsigned sbase = smem_u32(asm_);
    const int tid  = threadIdx.x;
    const int lane = tid & 31;
    const int w    = tid >> 5;
    const int gid  = lane >> 2, tig = lane & 3;
    const int qt = blockIdx.x & 15;
    const int sp = blockIdx.x >> 4;
    const int h = blockIdx.y, b = blockIdx.z;
    const size_t bh = (size_t)(b*NH + h) * SEQ;
    const size_t kvbase = bh + (size_t)sp * (SEQ/2);

    float* Op = Opart + (size_t)sp * ((size_t)MROWS * DM);
    float* Lp = Lpart + (size_t)sp * ((size_t)NB * NH * SEQ);

    const int kvplane = tid >> 6, kvrow = tid & 63;
    const u16* kvsrc[4] = {Khh, Khl, Vhh, Vhl};
    const unsigned kvoff[4] = {0u, 9216u, 18432u, 27648u};

    {
        const u16* src = kvsrc[kvplane] + ((kvbase + kvrow) << 6);
        unsigned dst = sbase + ABUF0 + kvoff[kvplane] + kvrow * 144;
#pragma unroll
        for (int i = 0; i < 8; i++) CP_ASYNC16(dst + i*16, src + i*8);
        CP_COMMIT();
    }
    {
        int plane = tid >> 7, row = tid & 127;
        const u16* src = (plane ? Qhl : Qhh) + ((bh + qt*128 + row) << 6);
        unsigned dstoff = (plane ? AQL : AQH) + row * 144;
#pragma unroll
        for (int i = 0; i < 8; i++) {
            uint4 v = *(const uint4*)(src + i*8);
            *(uint4*)(asm_ + dstoff + i*16) = v;
        }
    }
    CP_WAIT0();
    __syncthreads();

    u32 qfh[4][4], qfl[4][4];
    {
        unsigned rbase = (unsigned)(w*16 + (lane & 15)) * 144 + (lane >> 4) * 16;
#pragma unroll
        for (int ks = 0; ks < 4; ks++) {
            ldsm4(qfh[ks][0], qfh[ks][1], qfh[ks][2], qfh[ks][3],
                  sbase + AQH + rbase + ks*32);
            ldsm4(qfl[ks][0], qfl[ks][1], qfl[ks][2], qfl[ks][3],
                  sbase + AQL + rbase + ks*32);
        }
    }

    float o_[8][4];
#pragma unroll
    for (int j = 0; j < 8; j++)
#pragma unroll
        for (int t = 0; t < 4; t++) o_[j][t] = 0.f;
    float l0 = 0.f, l1 = 0.f;

    const unsigned b_rowoff = ((lane & 7) + ((lane & 16) >> 1)) * 144 + (lane & 8) * 2;
    const unsigned v_rowoff = (lane & 15) * 144 + (lane >> 4) * 16;

    for (int kt = 0; kt < NKT; kt++) {
        const unsigned cbuf = (kt & 1) ? ABUF1 : ABUF0;

        if (kt + 1 < NKT) {
            const u16* src = kvsrc[kvplane] + ((kvbase + (kt+1)*64 + kvrow) << 6);
            unsigned dst = sbase + ((kt & 1) ? ABUF0 : ABUF1) + kvoff[kvplane]
                         + kvrow * 144;
#pragma unroll
            for (int i = 0; i < 8; i++) CP_ASYNC16(dst + i*16, src + i*8);
            CP_COMMIT();
        }

        float s_[8][4];
#pragma unroll
        for (int j = 0; j < 8; j++)
#pragma unroll
            for (int t = 0; t < 4; t++) s_[j][t] = 0.f;
#pragma unroll
        for (int ks = 0; ks < 4; ks++) {
#pragma unroll
            for (int ng = 0; ng < 4; ng++) {
                unsigned roff = (unsigned)(ng*16)*144 + b_rowoff + ks*32;
                u32 bhv[4], blv[4];
                ldsm4(bhv[0], bhv[1], bhv[2], bhv[3], sbase + cbuf + 0u    + roff);
                ldsm4(blv[0], blv[1], blv[2], blv[3], sbase + cbuf + 9216u + roff);
                mma16816(s_[2*ng+0], qfh[ks], &bhv[0]);
                mma16816(s_[2*ng+0], qfh[ks], &blv[0]);
                mma16816(s_[2*ng+0], qfl[ks], &bhv[0]);
                mma16816(s_[2*ng+1], qfh[ks], &bhv[2]);
                mma16816(s_[2*ng+1], qfh[ks], &blv[2]);
                mma16816(s_[2*ng+1], qfl[ks], &bhv[2]);
            }
        }

#pragma unroll
        for (int ks = 0; ks < 4; ks++) {
            float p0 = fexp(s_[2*ks+0][0]);
            float p1 = fexp(s_[2*ks+0][1]);
            float p2 = fexp(s_[2*ks+0][2]);
            float p3 = fexp(s_[2*ks+0][3]);
            float q0 = fexp(s_[2*ks+1][0]);
            float q1 = fexp(s_[2*ks+1][1]);
            float q2 = fexp(s_[2*ks+1][2]);
            float q3 = fexp(s_[2*ks+1][3]);
            l0 += (p0 + p1) + (q0 + q1);
            l1 += (p2 + p3) + (q2 + q3);
            float h0 = truncbf(p0), h1 = truncbf(p1), h2 = truncbf(p2), h3 = truncbf(p3);
            float g0 = truncbf(q0), g1 = truncbf(q1), g2 = truncbf(q2), g3 = truncbf(q3);
            u32 pah[4], pal[4];
            pah[0] = packbf(h0, h1); pah[1] = packbf(h2, h3);
            pah[2] = packbf(g0, g1); pah[3] = packbf(g2, g3);
            pal[0] = packbf(p0 - h0, p1 - h1); pal[1] = packbf(p2 - h2, p3 - h3);
            pal[2] = packbf(q0 - g0, q1 - g1); pal[3] = packbf(q2 - g2, q3 - g3);

            unsigned rbase = (unsigned)(ks*16)*144 + v_rowoff;
#pragma unroll
            for (int ng = 0; ng < 4; ng++) {
                unsigned roff = rbase + (unsigned)(ng*32);
                u32 vh[4], vl[4];
                ldsm4t(vh[0], vh[1], vh[2], vh[3], sbase + cbuf + 18432u + roff);
                ldsm4t(vl[0], vl[1], vl[2], vl[3], sbase + cbuf + 27648u + roff);
                mma16816(o_[2*ng+0], pah, &vh[0]);
                mma16816(o_[2*ng+0], pal, &vh[0]);
                mma16816(o_[2*ng+0], pah, &vl[0]);
                mma16816(o_[2*ng+1], pah, &vh[2]);
                mma16816(o_[2*ng+1], pal, &vh[2]);
                mma16816(o_[2*ng+1], pah, &vl[2]);
            }
        }

        CP_WAIT0();
        __syncthreads();
    }

    l0 += __shfl_xor_sync(0xffffffffu, l0, 1);
    l0 += __shfl_xor_sync(0xffffffffu, l0, 2);
    l1 += __shfl_xor_sync(0xffffffffu, l1, 1);
    l1 += __shfl_xor_sync(0xffffffffu, l1, 2);

    int r0 = qt*128 + w*16 + gid;
    size_t ob0 = (bh + r0) << 6;
    size_t ob1 = (bh + r0 + 8) << 6;
#pragma unroll
    for (int j = 0; j < 8; j++) {
        int d = j*8 + tig*2;
        *(float2*)(Op + ob0 + d) = make_float2(o_[j][0], o_[j][1]);
        *(float2*)(Op + ob1 + d) = make_float2(o_[j][2], o_[j][3]);
    }
    if (tig == 0) {
        Lp[bh + r0]     = l0;
        Lp[bh + r0 + 8] = l1;
    }
}

extern "C" void kernel_launch(void* const* d_in, const int* in_sizes, int n_in,
                              void* d_out, int out_size)
{
    const float* q    = (const float*)d_in[0];
    const float* k    = (const float*)d_in[1];
    const float* v    = (const float*)d_in[2];
    const float* wq_w = (const float*)d_in[3];
    const float* wq_b = (const float*)d_in[4];
    const float* wk_w = (const float*)d_in[5];
    const float* wk_b = (const float*)d_in[6];
    const float* wv_w = (const float*)d_in[7];
    const float* wv_b = (const float*)d_in[8];
    const float* wo_w = (const float*)d_in[9];
    const float* wo_b = (const float*)d_in[10];
    float* out = (float*)d_out;

    u16 *ah, *al, *wh0, *wl0, *qhh, *qhl, *khh, *khl, *vhh, *vhl, *ch, *cl;
    float *op, *lp;
    cudaGetSymbolAddress((void**)&ah,  g_ah);
    cudaGetSymbolAddress((void**)&al,  g_al);
    cudaGetSymbolAddress((void**)&wh0, g_w_h);
    cudaGetSymbolAddress((void**)&wl0, g_w_l);
    cudaGetSymbolAddress((void**)&qhh, g_qhh);
    cudaGetSymbolAddress((void**)&qhl, g_qhl);
    cudaGetSymbolAddress((void**)&khh, g_khh);
    cudaGetSymbolAddress((void**)&khl, g_khl);
    cudaGetSymbolAddress((void**)&vhh, g_vhh);
    cudaGetSymbolAddress((void**)&vhl, g_vhl);
    cudaGetSymbolAddress((void**)&ch,  g_ch);
    cudaGetSymbolAddress((void**)&cl,  g_cl);
    cudaGetSymbolAddress((void**)&op,  g_opart);
    cudaGetSymbolAddress((void**)&lp,  g_lpart);
    const size_t WSZ = (size_t)DM * DM;
    const size_t OSZ = (size_t)MROWS * DM;
    const size_t LSZ = (size_t)NB * NH * SEQ;

    cudaFuncSetAttribute(gemm_mma2,
                         cudaFuncAttributeMaxDynamicSharedMemorySize, GSMEM_BYTES);
    cudaFuncSetAttribute(attn_mma_kernel,
                         cudaFuncAttributeMaxDynamicSharedMemorySize, ASMEM_BYTES);

    const int nW4 = DM*DM/4, nA4 = MROWS*DM/4;
    const int cblk = 256;
    const int cgW = (nW4 + cblk - 1) / cblk;
    const int cgA = (nA4 + cblk - 1) / cblk;

    conv_split<<<cgW, cblk>>>((const float4*)wq_w, (uint2*)(wh0 + 0*WSZ), (uint2*)(wl0 + 0*WSZ), nW4);
    conv_split<<<cgW, cblk>>>((const float4*)wk_w, (uint2*)(wh0 + 1*WSZ), (uint2*)(wl0 + 1*WSZ), nW4);
    conv_split<<<cgW, cblk>>>((const float4*)wv_w, (uint2*)(wh0 + 2*WSZ), (uint2*)(wl0 + 2*WSZ), nW4);
    conv_split<<<cgW, cblk>>>((const float4*)wo_w, (uint2*)(wh0 + 3*WSZ), (uint2*)(wl0 + 3*WSZ), nW4);

    dim3 gblk(256), ggrid(DM/128, MROWS/128);

    conv_split<<<cgA, cblk>>>((const float4*)q, (uint2*)ah, (uint2*)al, nA4);
    gemm_mma2<<<ggrid, gblk, GSMEM_BYTES>>>(ah, al, wh0 + 0*WSZ, wl0 + 0*WSZ,
                                            wq_b, nullptr, qhh, qhl, 1, 0.125f);
    conv_split<<<cgA, cblk>>>((const float4*)k, (uint2*)ah, (uint2*)al, nA4);
    gemm_mma2<<<ggrid, gblk, GSMEM_BYTES>>>(ah, al, wh0 + 1*WSZ, wl0 + 1*WSZ,
                                            wk_b, nullptr, khh, khl, 1, 1.0f);
    conv_split<<<cgA, cblk>>>((const float4*)v, (uint2*)ah, (uint2*)al, nA4);
    gemm_mma2<<<ggrid, gblk, GSMEM_BYTES>>>(ah, al, wh0 + 2*WSZ, wl0 + 2*WSZ,
                                            wv_b, nullptr, vhh, vhl, 1, 1.0f);

    dim3 ablk(256), agrid(32, NH, NB);
    attn_mma_kernel<<<agrid, ablk, ASMEM_BYTES>>>(qhh, qhl, khh, khl, vhh, vhl,
                                                  op, lp);

    merge_ctx<<<(int)(OSZ/4/cblk), cblk>>>((const float4*)op,
                                           (const float4*)(op + OSZ),
                                           lp, lp + LSZ, ch, cl);

    gemm_mma2<<<ggrid, gblk, GSMEM_BYTES>>>(ch, cl, wh0 + 3*WSZ, wl0 + 3*WSZ,
                                            wo_b, out, nullptr, nullptr, 0, 1.0f);
}

// round 9
// speedup vs baseline: 1.0183x; 1.0183x over previous
#include <cuda_runtime.h>
#include <cstdint>

#define NB   4
#define SEQ  2048
#define NH   16
#define DEP  64
#define DM   1024
#define MROWS (NB*SEQ)

typedef unsigned short u16;
typedef unsigned int   u32;

__device__ u16 g_ah [(size_t)MROWS*DM];
__device__ u16 g_al [(size_t)MROWS*DM];
__device__ u16 g_w_h[4][(size_t)DM*DM];
__device__ u16 g_w_l[4][(size_t)DM*DM];
__device__ u16 g_qhh[(size_t)MROWS*DM];
__device__ u16 g_qhl[(size_t)MROWS*DM];
__device__ u16 g_khh[(size_t)MROWS*DM];
__device__ u16 g_khl[(size_t)MROWS*DM];
__device__ u16 g_vhh[(size_t)MROWS*DM];
__device__ u16 g_vhl[(size_t)MROWS*DM];
__device__ u16 g_ch [(size_t)MROWS*DM];
__device__ u16 g_cl [(size_t)MROWS*DM];

__device__ __forceinline__ unsigned smem_u32(const void* p) {
    unsigned r;
    asm("{ .reg .u64 t; cvta.to.shared.u64 t, %1; cvt.u32.u64 %0, t; }"
        : "=r"(r) : "l"(p));
    return r;
}

__device__ __forceinline__ void ldsm4(u32& r0, u32& r1, u32& r2, u32& r3,
                                      unsigned addr) {
    asm volatile("ldmatrix.sync.aligned.m8n8.x4.shared.b16 {%0,%1,%2,%3}, [%4];"
                 : "=r"(r0), "=r"(r1), "=r"(r2), "=r"(r3) : "r"(addr));
}
__device__ __forceinline__ void ldsm4t(u32& r0, u32& r1, u32& r2, u32& r3,
                                       unsigned addr) {
    asm volatile("ldmatrix.sync.aligned.m8n8.x4.trans.shared.b16 {%0,%1,%2,%3}, [%4];"
                 : "=r"(r0), "=r"(r1), "=r"(r2), "=r"(r3) : "r"(addr));
}
__device__ __forceinline__ void mma16816(float* d, const u32* a, const u32* b) {
    asm volatile("mma.sync.aligned.m16n8k16.row.col.f32.bf16.bf16.f32 "
                 "{%0,%1,%2,%3}, {%4,%5,%6,%7}, {%8,%9}, {%0,%1,%2,%3};"
                 : "+f"(d[0]), "+f"(d[1]), "+f"(d[2]), "+f"(d[3])
                 : "r"(a[0]), "r"(a[1]), "r"(a[2]), "r"(a[3]),
                   "r"(b[0]), "r"(b[1]));
}

#define CP_ASYNC16(dst, src) \
    asm volatile("cp.async.cg.shared.global [%0], [%1], 16;" :: "r"(dst), "l"(src))
#define CP_COMMIT() asm volatile("cp.async.commit_group;" ::: "memory")
#define CP_WAIT0()  asm volatile("cp.async.wait_group 0;" ::: "memory")

__device__ __forceinline__ float fexp(float x) {
    float z  = fmaxf(x * 1.4426950408889634f, -126.0f);
    float zi = z + 12582912.0f;
    int   n  = __float_as_int(zi);
    float f  = zi - 12582912.0f;
    float r  = z - f;
    float p  = 0.0013333558f;
    p = fmaf(p, r, 0.0096181291f);
    p = fmaf(p, r, 0.0555041087f);
    p = fmaf(p, r, 0.2402265069f);
    p = fmaf(p, r, 0.6931471806f);
    p = fmaf(p, r, 1.0f);
    int bits = __float_as_int(p) + (int)((unsigned)n << 23);
    return __int_as_float(bits);
}

__device__ __forceinline__ void split4(float4 v, uint2& hi, uint2& lo) {
    unsigned b0 = __float_as_uint(v.x), b1 = __float_as_uint(v.y);
    unsigned b2 = __float_as_uint(v.z), b3 = __float_as_uint(v.w);
    hi.x = __byte_perm(b0, b1, 0x7632);
    hi.y = __byte_perm(b2, b3, 0x7632);
    float r0 = v.x - __uint_as_float(b0 & 0xffff0000u);
    float r1 = v.y - __uint_as_float(b1 & 0xffff0000u);
    float r2 = v.z - __uint_as_float(b2 & 0xffff0000u);
    float r3 = v.w - __uint_as_float(b3 & 0xffff0000u);
    lo.x = __byte_perm(__float_as_uint(r0), __float_as_uint(r1), 0x7632);
    lo.y = __byte_perm(__float_as_uint(r2), __float_as_uint(r3), 0x7632);
}

__device__ __forceinline__ u32 packbf(float a, float b) {
    return __byte_perm(__float_as_uint(a), __float_as_uint(b), 0x7632);
}
__device__ __forceinline__ float truncbf(float a) {
    return __uint_as_float(__float_as_uint(a) & 0xffff0000u);
}

__global__ void conv_split(const float4* __restrict__ src,
                           uint2* __restrict__ hi, uint2* __restrict__ lo, int n4)
{
    int i = blockIdx.x * blockDim.x + threadIdx.x;
    if (i >= n4) return;
    float4 v = src[i];
    uint2 h, l;
    split4(v, h, l);
    hi[i] = h; lo[i] = l;
}

// ---------------- GEMM (unchanged; at HMMA floor) ----------------
#define GP 40
#define STAGE_B 40960
#define GSMEM_BYTES (2*STAGE_B)

#define GEMM_ISSUE(chunk, stage) do { \
    unsigned _db = sbase + (stage)*STAGE_B; \
    int _ck = (chunk) * 32; \
    _Pragma("unroll") \
    for (int _i = 0; _i < 8; _i++) { \
        int _pl = _i >> 1; \
        int _row = ((_i & 1) << 6) + trow; \
        const u16* _s = srcs[_pl] + (size_t)_row * DM + _ck + tc16 * 8; \
        unsigned _d = _db + _pl * 10240 + _row * 80 + tc16 * 16; \
        CP_ASYNC16(_d, _s); \
    } \
    CP_COMMIT(); \
} while (0)

__global__ void __launch_bounds__(256, 2) gemm_mma2(
    const u16* __restrict__ Ah, const u16* __restrict__ Al,
    const u16* __restrict__ Wh, const u16* __restrict__ Wl,
    const float* __restrict__ bias,
    float* __restrict__ Cf, u16* __restrict__ Ch, u16* __restrict__ Cl,
    int mode, float scale)
{
    extern __shared__ char gsm[];
    const unsigned sbase = smem_u32(gsm);
    const int tid  = threadIdx.x;
    const int lane = tid & 31;
    const int warp = tid >> 5;
    const int warp_m = warp & 1, warp_n = warp >> 1;
    const int bn = blockIdx.x, bm = blockIdx.y;

    const u16* srcs[4];
    srcs[0] = Ah + (size_t)(bm * 128) * DM;
    srcs[1] = Al + (size_t)(bm * 128) * DM;
    srcs[2] = Wh + (size_t)(bn * 128) * DM;
    srcs[3] = Wl + (size_t)(bn * 128) * DM;

    const int trow = tid >> 2;
    const int tc16 = tid & 3;

    float acc[4][4][4];
#pragma unroll
    for (int i = 0; i < 4; i++)
#pragma unroll
        for (int j = 0; j < 4; j++)
#pragma unroll
            for (int t = 0; t < 4; t++) acc[i][j][t] = 0.f;

    const unsigned OFF_AH = 0, OFF_AL = 10240, OFF_WH = 20480, OFF_WL = 30720;
    const unsigned a_row = warp_m*64 + (lane & 15);
    const unsigned a_kof = (lane >> 4) * 8;
    const unsigned b_row = warp_n*32 + (lane & 7) + ((lane & 16) >> 1);
    const unsigned b_kof = (lane & 8);

    GEMM_ISSUE(0, 0);

    const int NCHUNK = DM / 32;
    for (int c = 0; c < NCHUNK; c++) {
        CP_WAIT0();
        __syncthreads();
        if (c + 1 < NCHUNK) GEMM_ISSUE(c + 1, (c + 1) & 1);

        const unsigned st = sbase + (unsigned)(c & 1) * STAGE_B;
#pragma unroll
        for (int ks = 0; ks < 2; ks++) {
            const unsigned kbyte = (unsigned)(ks * 16) * 2;
            u32 bh[8], bl[8];
#pragma unroll
            for (int jp = 0; jp < 2; jp++) {
                unsigned roff = (b_row + jp*16) * (GP*2) + kbyte + b_kof*2;
                ldsm4(bh[jp*4+0], bh[jp*4+1], bh[jp*4+2], bh[jp*4+3],
                      st + OFF_WH + roff);
                ldsm4(bl[jp*4+0], bl[jp*4+1], bl[jp*4+2], bl[jp*4+3],
                      st + OFF_WL + roff);
            }
#pragma unroll
            for (int i = 0; i < 4; i++) {
                unsigned roff = (a_row + i*16) * (GP*2) + kbyte + a_kof*2;
                u32 ah[4], al[4];
                ldsm4(ah[0], ah[1], ah[2], ah[3], st + OFF_AH + roff);
                ldsm4(al[0], al[1], al[2], al[3], st + OFF_AL + roff);
#pragma unroll
                for (int j = 0; j < 4; j++) {
                    mma16816(acc[i][j], ah, &bh[j*2]);
                    mma16816(acc[i][j], ah, &bl[j*2]);
                    mma16816(acc[i][j], al, &bh[j*2]);
                }
            }
        }
        __syncthreads();
    }

    const int gid = lane >> 2, tig = lane & 3;
#pragma unroll
    for (int i = 0; i < 4; i++) {
#pragma unroll
        for (int j = 0; j < 4; j++) {
            int gnc = bn*128 + warp_n*32 + j*8 + tig*2;
            float2 bv = *(const float2*)(bias + gnc);
#pragma unroll
            for (int half = 0; half < 2; half++) {
                int m = bm*128 + warp_m*64 + i*16 + gid + half*8;
                float o0 = (acc[i][j][half*2+0] + bv.x) * scale;
                float o1 = (acc[i][j][half*2+1] + bv.y) * scale;
                if (mode == 0) {
                    *(float2*)(Cf + (size_t)m * DM + gnc) = make_float2(o0, o1);
                } else {
                    int bi = m >> 11, s = m & (SEQ - 1);
                    int hh = gnc >> 6, d = gnc & 63;
                    size_t idx = (((size_t)(bi*NH + hh) * SEQ + s) << 6) + d;
                    float h0 = truncbf(o0), h1 = truncbf(o1);
                    *(u32*)(Ch + idx) = packbf(h0, h1);
                    *(u32*)(Cl + idx) = packbf(o0 - h0, o1 - h1);
                }
            }
        }
    }
}

// ---------------- attention: static-shift softmax + sw-pipelined frags ----
#define AQH 0
#define AQL 18432
#define ABUF0 36864
#define ABUF1 73728
#define ASMEM_BYTES 110592

__global__ void __launch_bounds__(256, 2) attn_mma_kernel(
    const u16* __restrict__ Qhh, const u16* __restrict__ Qhl,
    const u16* __restrict__ Khh, const u16* __restrict__ Khl,
    const u16* __restrict__ Vhh, const u16* __restrict__ Vhl,
    u16* __restrict__ Ch, u16* __restrict__ Cl)
{
    extern __shared__ char asm_[];
    const unsigned sbase = smem_u32(asm_);
    const int tid  = threadIdx.x;
    const int lane = tid & 31;
    const int w    = tid >> 5;
    const int gid  = lane >> 2, tig = lane & 3;
    const int qt = blockIdx.x, h = blockIdx.y, b = blockIdx.z;
    const size_t bh = (size_t)(b*NH + h) * SEQ;

    const int kvplane = tid >> 6, kvrow = tid & 63;
    const u16* kvsrc[4] = {Khh, Khl, Vhh, Vhl};
    const unsigned kvoff[4] = {0u, 9216u, 18432u, 27648u};

    {
        const u16* src = kvsrc[kvplane] + ((bh + kvrow) << 6);
        unsigned dst = sbase + ABUF0 + kvoff[kvplane] + kvrow * 144;
#pragma unroll
        for (int i = 0; i < 8; i++) CP_ASYNC16(dst + i*16, src + i*8);
        CP_COMMIT();
    }
    {
        int plane = tid >> 7, row = tid & 127;
        const u16* src = (plane ? Qhl : Qhh) + ((bh + qt*128 + row) << 6);
        unsigned dstoff = (plane ? AQL : AQH) + row * 144;
#pragma unroll
        for (int i = 0; i < 8; i++) {
            uint4 v = *(const uint4*)(src + i*8);
            *(uint4*)(asm_ + dstoff + i*16) = v;
        }
    }
    CP_WAIT0();
    __syncthreads();

    u32 qfh[4][4], qfl[4][4];
    {
        unsigned rbase = (unsigned)(w*16 + (lane & 15)) * 144 + (lane >> 4) * 16;
#pragma unroll
        for (int ks = 0; ks < 4; ks++) {
            ldsm4(qfh[ks][0], qfh[ks][1], qfh[ks][2], qfh[ks][3],
                  sbase + AQH + rbase + ks*32);
            ldsm4(qfl[ks][0], qfl[ks][1], qfl[ks][2], qfl[ks][3],
                  sbase + AQL + rbase + ks*32);
        }
    }

    float o_[8][4];
#pragma unroll
    for (int j = 0; j < 8; j++)
#pragma unroll
        for (int t = 0; t < 4; t++) o_[j][t] = 0.f;
    float l0 = 0.f, l1 = 0.f;

    const unsigned b_rowoff = ((lane & 7) + ((lane & 16) >> 1)) * 144 + (lane & 8) * 2;
    const unsigned v_rowoff = (lane & 15) * 144 + (lane >> 4) * 16;

    for (int kt = 0; kt < SEQ/64; kt++) {
        const unsigned cbuf = (kt & 1) ? ABUF1 : ABUF0;

        if (kt + 1 < SEQ/64) {
            const u16* src = kvsrc[kvplane] + ((bh + (kt+1)*64 + kvrow) << 6);
            unsigned dst = sbase + ((kt & 1) ? ABUF0 : ABUF1) + kvoff[kvplane]
                         + kvrow * 144;
#pragma unroll
            for (int i = 0; i < 8; i++) CP_ASYNC16(dst + i*16, src + i*8);
            CP_COMMIT();
        }

        // ---- QK^T: flattened (ks,ng), K-frags double-buffered ----
        float s_[8][4];
#pragma unroll
        for (int j = 0; j < 8; j++)
#pragma unroll
            for (int t = 0; t < 4; t++) s_[j][t] = 0.f;

        u32 kh2[2][4], kl2[2][4];
        ldsm4(kh2[0][0], kh2[0][1], kh2[0][2], kh2[0][3],
              sbase + cbuf + 0u    + b_rowoff);
        ldsm4(kl2[0][0], kl2[0][1], kl2[0][2], kl2[0][3],
              sbase + cbuf + 9216u + b_rowoff);
#pragma unroll
        for (int it = 0; it < 16; it++) {
            const int ks = it >> 2, ng = it & 3;
            const int cur = it & 1;
            if (it + 1 < 16) {
                const int ks2 = (it + 1) >> 2, ng2 = (it + 1) & 3;
                unsigned roff = (unsigned)(ng2*16)*144 + b_rowoff + ks2*32;
                ldsm4(kh2[cur^1][0], kh2[cur^1][1], kh2[cur^1][2], kh2[cur^1][3],
                      sbase + cbuf + 0u    + roff);
                ldsm4(kl2[cur^1][0], kl2[cur^1][1], kl2[cur^1][2], kl2[cur^1][3],
                      sbase + cbuf + 9216u + roff);
            }
            mma16816(s_[2*ng+0], qfh[ks], &kh2[cur][0]);
            mma16816(s_[2*ng+0], qfh[ks], &kl2[cur][0]);
            mma16816(s_[2*ng+0], qfl[ks], &kh2[cur][0]);
            mma16816(s_[2*ng+1], qfh[ks], &kh2[cur][2]);
            mma16816(s_[2*ng+1], qfh[ks], &kl2[cur][2]);
            mma16816(s_[2*ng+1], qfl[ks], &kh2[cur][2]);
        }

        // ---- PV: flattened (ks,ng), V-frags double-buffered; pack per ks ----
        u32 vh2[2][4], vl2[2][4];
        ldsm4t(vh2[0][0], vh2[0][1], vh2[0][2], vh2[0][3],
               sbase + cbuf + 18432u + v_rowoff);
        ldsm4t(vl2[0][0], vl2[0][1], vl2[0][2], vl2[0][3],
               sbase + cbuf + 27648u + v_rowoff);
        u32 pah[4], pal[4];
#pragma unroll
        for (int it = 0; it < 16; it++) {
            const int ks = it >> 2, ng = it & 3;
            const int cur = it & 1;
            if (it + 1 < 16) {
                const int ks2 = (it + 1) >> 2, ng2 = (it + 1) & 3;
                unsigned roff = (unsigned)(ks2*16)*144 + v_rowoff + (unsigned)(ng2*32);
                ldsm4t(vh2[cur^1][0], vh2[cur^1][1], vh2[cur^1][2], vh2[cur^1][3],
                       sbase + cbuf + 18432u + roff);
                ldsm4t(vl2[cur^1][0], vl2[cur^1][1], vl2[cur^1][2], vl2[cur^1][3],
                       sbase + cbuf + 27648u + roff);
            }
            if (ng == 0) {
                float p0 = fexp(s_[2*ks+0][0]);
                float p1 = fexp(s_[2*ks+0][1]);
                float p2 = fexp(s_[2*ks+0][2]);
                float p3 = fexp(s_[2*ks+0][3]);
                float q0 = fexp(s_[2*ks+1][0]);
                float q1 = fexp(s_[2*ks+1][1]);
                float q2 = fexp(s_[2*ks+1][2]);
                float q3 = fexp(s_[2*ks+1][3]);
                l0 += (p0 + p1) + (q0 + q1);
                l1 += (p2 + p3) + (q2 + q3);
                float h0 = truncbf(p0), h1 = truncbf(p1);
                float h2 = truncbf(p2), h3 = truncbf(p3);
                float g0 = truncbf(q0), g1 = truncbf(q1);
                float g2 = truncbf(q2), g3 = truncbf(q3);
                pah[0] = packbf(h0, h1); pah[1] = packbf(h2, h3);
                pah[2] = packbf(g0, g1); pah[3] = packbf(g2, g3);
                pal[0] = packbf(p0 - h0, p1 - h1);
                pal[1] = packbf(p2 - h2, p3 - h3);
                pal[2] = packbf(q0 - g0, q1 - g1);
                pal[3] = packbf(q2 - g2, q3 - g3);
            }
            mma16816(o_[2*ng+0], pah, &vh2[cur][0]);
            mma16816(o_[2*ng+0], pal, &vh2[cur][0]);
            mma16816(o_[2*ng+0], pah, &vl2[cur][0]);
            mma16816(o_[2*ng+1], pah, &vh2[cur][2]);
            mma16816(o_[2*ng+1], pal, &vh2[cur][2]);
            mma16816(o_[2*ng+1], pah, &vl2[cur][2]);
        }

        CP_WAIT0();
        __syncthreads();
    }

    l0 += __shfl_xor_sync(0xffffffffu, l0, 1);
    l0 += __shfl_xor_sync(0xffffffffu, l0, 2);
    l1 += __shfl_xor_sync(0xffffffffu, l1, 1);
    l1 += __shfl_xor_sync(0xffffffffu, l1, 2);

    float inv0 = 1.f / l0, inv1 = 1.f / l1;
    int r0 = qt*128 + w*16 + gid;
    size_t base0 = ((size_t)(b*SEQ) + r0) * DM + h*64;
    size_t base1 = base0 + (size_t)8 * DM;
#pragma unroll
    for (int j = 0; j < 8; j++) {
        int d = j*8 + tig*2;
        float a0 = o_[j][0] * inv0, a1 = o_[j][1] * inv0;
        float h0 = truncbf(a0), h1 = truncbf(a1);
        *(u32*)(Ch + base0 + d) = packbf(h0, h1);
        *(u32*)(Cl + base0 + d) = packbf(a0 - h0, a1 - h1);
        float c0 = o_[j][2] * inv1, c1 = o_[j][3] * inv1;
        float g0 = truncbf(c0), g1 = truncbf(c1);
        *(u32*)(Ch + base1 + d) = packbf(g0, g1);
        *(u32*)(Cl + base1 + d) = packbf(c0 - g0, c1 - g1);
    }
}

extern "C" void kernel_launch(void* const* d_in, const int* in_sizes, int n_in,
                              void* d_out, int out_size)
{
    const float* q    = (const float*)d_in[0];
    const float* k    = (const float*)d_in[1];
    const float* v    = (const float*)d_in[2];
    const float* wq_w = (const float*)d_in[3];
    const float* wq_b = (const float*)d_in[4];
    const float* wk_w = (const float*)d_in[5];
    const float* wk_b = (const float*)d_in[6];
    const float* wv_w = (const float*)d_in[7];
    const float* wv_b = (const float*)d_in[8];
    const float* wo_w = (const float*)d_in[9];
    const float* wo_b = (const float*)d_in[10];
    float* out = (float*)d_out;

    u16 *ah, *al, *wh0, *wl0, *qhh, *qhl, *khh, *khl, *vhh, *vhl, *ch, *cl;
    cudaGetSymbolAddress((void**)&ah,  g_ah);
    cudaGetSymbolAddress((void**)&al,  g_al);
    cudaGetSymbolAddress((void**)&wh0, g_w_h);
    cudaGetSymbolAddress((void**)&wl0, g_w_l);
    cudaGetSymbolAddress((void**)&qhh, g_qhh);
    cudaGetSymbolAddress((void**)&qhl, g_qhl);
    cudaGetSymbolAddress((void**)&khh, g_khh);
    cudaGetSymbolAddress((void**)&khl, g_khl);
    cudaGetSymbolAddress((void**)&vhh, g_vhh);
    cudaGetSymbolAddress((void**)&vhl, g_vhl);
    cudaGetSymbolAddress((void**)&ch,  g_ch);
    cudaGetSymbolAddress((void**)&cl,  g_cl);
    const size_t WSZ = (size_t)DM * DM;

    cudaFuncSetAttribute(gemm_mma2,
                         cudaFuncAttributeMaxDynamicSharedMemorySize, GSMEM_BYTES);
    cudaFuncSetAttribute(attn_mma_kernel,
                         cudaFuncAttributeMaxDynamicSharedMemorySize, ASMEM_BYTES);

    const int nW4 = DM*DM/4, nA4 = MROWS*DM/4;
    const int cblk = 256;
    const int cgW = (nW4 + cblk - 1) / cblk;
    const int cgA = (nA4 + cblk - 1) / cblk;

    conv_split<<<cgW, cblk>>>((const float4*)wq_w, (uint2*)(wh0 + 0*WSZ), (uint2*)(wl0 + 0*WSZ), nW4);
    conv_split<<<cgW, cblk>>>((const float4*)wk_w, (uint2*)(wh0 + 1*WSZ), (uint2*)(wl0 + 1*WSZ), nW4);
    conv_split<<<cgW, cblk>>>((const float4*)wv_w, (uint2*)(wh0 + 2*WSZ), (uint2*)(wl0 + 2*WSZ), nW4);
    conv_split<<<cgW, cblk>>>((const float4*)wo_w, (uint2*)(wh0 + 3*WSZ), (uint2*)(wl0 + 3*WSZ), nW4);

    dim3 gblk(256), ggrid(DM/128, MROWS/128);

    conv_split<<<cgA, cblk>>>((const float4*)q, (uint2*)ah, (uint2*)al, nA4);
    gemm_mma2<<<ggrid, gblk, GSMEM_BYTES>>>(ah, al, wh0 + 0*WSZ, wl0 + 0*WSZ,
                                            wq_b, nullptr, qhh, qhl, 1, 0.125f);
    conv_split<<<cgA, cblk>>>((const float4*)k, (uint2*)ah, (uint2*)al, nA4);
    gemm_mma2<<<ggrid, gblk, GSMEM_BYTES>>>(ah, al, wh0 + 1*WSZ, wl0 + 1*WSZ,
                                            wk_b, nullptr, khh, khl, 1, 1.0f);
    conv_split<<<cgA, cblk>>>((const float4*)v, (uint2*)ah, (uint2*)al, nA4);
    gemm_mma2<<<ggrid, gblk, GSMEM_BYTES>>>(ah, al, wh0 + 2*WSZ, wl0 + 2*WSZ,
                                            wv_b, nullptr, vhh, vhl, 1, 1.0f);

    dim3 ablk(256), agrid(SEQ/128, NH, NB);
    attn_mma_kernel<<<agrid, ablk, ASMEM_BYTES>>>(qhh, qhl, khh, khl, vhh, vhl,
                                                  ch, cl);

    gemm_mma2<<<ggrid, gblk, GSMEM_BYTES>>>(ch, cl, wh0 + 3*WSZ, wl0 + 3*WSZ,
                                            wo_b, out, nullptr, nullptr, 0, 1.0f);
}

// round 10
// speedup vs baseline: 1.4794x; 1.4527x over previous
#include <cuda_runtime.h>
#include <cstdint>

#define NB   4
#define SEQ  2048
#define NH   16
#define DEP  64
#define DM   1024
#define MROWS (NB*SEQ)

typedef unsigned short u16;
typedef unsigned int   u32;

// ---------------- scratch ----------------
__device__ u16 g_ah [(size_t)MROWS*DM];          // input bf16 hi/lo planes
__device__ u16 g_al [(size_t)MROWS*DM];
__device__ u16 g_w_h[4][(size_t)DM*DM];          // weights bf16 hi/lo
__device__ u16 g_w_l[4][(size_t)DM*DM];
__device__ u16 g_q16[(size_t)MROWS*DM];          // fp16 head planes [B,H,S,64]
__device__ u16 g_k16[(size_t)MROWS*DM];
__device__ u16 g_v16[(size_t)MROWS*DM];
__device__ u16 g_ch [(size_t)MROWS*DM];          // ctx bf16 hi/lo [B,S,DM]
__device__ u16 g_cl [(size_t)MROWS*DM];

// ---------------- helpers ----------------
__device__ __forceinline__ unsigned smem_u32(const void* p) {
    unsigned r;
    asm("{ .reg .u64 t; cvta.to.shared.u64 t, %1; cvt.u32.u64 %0, t; }"
        : "=r"(r) : "l"(p));
    return r;
}

__device__ __forceinline__ void ldsm4(u32& r0, u32& r1, u32& r2, u32& r3,
                                      unsigned addr) {
    asm volatile("ldmatrix.sync.aligned.m8n8.x4.shared.b16 {%0,%1,%2,%3}, [%4];"
                 : "=r"(r0), "=r"(r1), "=r"(r2), "=r"(r3) : "r"(addr));
}
__device__ __forceinline__ void ldsm4t(u32& r0, u32& r1, u32& r2, u32& r3,
                                       unsigned addr) {
    asm volatile("ldmatrix.sync.aligned.m8n8.x4.trans.shared.b16 {%0,%1,%2,%3}, [%4];"
                 : "=r"(r0), "=r"(r1), "=r"(r2), "=r"(r3) : "r"(addr));
}
// bf16 mma (GEMM path)
__device__ __forceinline__ void mma16816(float* d, const u32* a, const u32* b) {
    asm volatile("mma.sync.aligned.m16n8k16.row.col.f32.bf16.bf16.f32 "
                 "{%0,%1,%2,%3}, {%4,%5,%6,%7}, {%8,%9}, {%0,%1,%2,%3};"
                 : "+f"(d[0]), "+f"(d[1]), "+f"(d[2]), "+f"(d[3])
                 : "r"(a[0]), "r"(a[1]), "r"(a[2]), "r"(a[3]),
                   "r"(b[0]), "r"(b[1]));
}
// fp16 mma (attention path)
__device__ __forceinline__ void mma16816h(float* d, const u32* a, const u32* b) {
    asm volatile("mma.sync.aligned.m16n8k16.row.col.f32.f16.f16.f32 "
                 "{%0,%1,%2,%3}, {%4,%5,%6,%7}, {%8,%9}, {%0,%1,%2,%3};"
                 : "+f"(d[0]), "+f"(d[1]), "+f"(d[2]), "+f"(d[3])
                 : "r"(a[0]), "r"(a[1]), "r"(a[2]), "r"(a[3]),
                   "r"(b[0]), "r"(b[1]));
}

#define CP_ASYNC16(dst, src) \
    asm volatile("cp.async.cg.shared.global [%0], [%1], 16;" :: "r"(dst), "l"(src))
#define CP_COMMIT() asm volatile("cp.async.commit_group;" ::: "memory")
#define CP_WAIT0()  asm volatile("cp.async.wait_group 0;" ::: "memory")

__device__ __forceinline__ float fexp(float x) {
    float z  = fmaxf(x * 1.4426950408889634f, -126.0f);
    float zi = z + 12582912.0f;
    int   n  = __float_as_int(zi);
    float f  = zi - 12582912.0f;
    float r  = z - f;
    float p  = 0.0013333558f;
    p = fmaf(p, r, 0.0096181291f);
    p = fmaf(p, r, 0.0555041087f);
    p = fmaf(p, r, 0.2402265069f);
    p = fmaf(p, r, 0.6931471806f);
    p = fmaf(p, r, 1.0f);
    int bits = __float_as_int(p) + (int)((unsigned)n << 23);
    return __int_as_float(bits);
}

__device__ __forceinline__ void split4(float4 v, uint2& hi, uint2& lo) {
    unsigned b0 = __float_as_uint(v.x), b1 = __float_as_uint(v.y);
    unsigned b2 = __float_as_uint(v.z), b3 = __float_as_uint(v.w);
    hi.x = __byte_perm(b0, b1, 0x7632);
    hi.y = __byte_perm(b2, b3, 0x7632);
    float r0 = v.x - __uint_as_float(b0 & 0xffff0000u);
    float r1 = v.y - __uint_as_float(b1 & 0xffff0000u);
    float r2 = v.z - __uint_as_float(b2 & 0xffff0000u);
    float r3 = v.w - __uint_as_float(b3 & 0xffff0000u);
    lo.x = __byte_perm(__float_as_uint(r0), __float_as_uint(r1), 0x7632);
    lo.y = __byte_perm(__float_as_uint(r2), __float_as_uint(r3), 0x7632);
}

__device__ __forceinline__ u32 packbf(float a, float b) {
    return __byte_perm(__float_as_uint(a), __float_as_uint(b), 0x7632);
}
__device__ __forceinline__ float truncbf(float a) {
    return __uint_as_float(__float_as_uint(a) & 0xffff0000u);
}
// pack two fp32 -> fp16x2 (round-to-nearest): lo = a, hi = b
__device__ __forceinline__ u32 packh2(float a, float b) {
    u32 d; asm("cvt.rn.f16x2.f32 %0, %1, %2;" : "=r"(d) : "f"(b), "f"(a));
    return d;
}

__global__ void conv_split(const float4* __restrict__ src,
                           uint2* __restrict__ hi, uint2* __restrict__ lo, int n4)
{
    int i = blockIdx.x * blockDim.x + threadIdx.x;
    if (i >= n4) return;
    float4 v = src[i];
    uint2 h, l;
    split4(v, h, l);
    hi[i] = h; lo[i] = l;
}

// ---------------- GEMM (bf16 hi/lo 3-mma; at HMMA floor) ----------------
#define GP 40
#define STAGE_B 40960
#define GSMEM_BYTES (2*STAGE_B)

#define GEMM_ISSUE(chunk, stage) do { \
    unsigned _db = sbase + (stage)*STAGE_B; \
    int _ck = (chunk) * 32; \
    _Pragma("unroll") \
    for (int _i = 0; _i < 8; _i++) { \
        int _pl = _i >> 1; \
        int _row = ((_i & 1) << 6) + trow; \
        const u16* _s = srcs[_pl] + (size_t)_row * DM + _ck + tc16 * 8; \
        unsigned _d = _db + _pl * 10240 + _row * 80 + tc16 * 16; \
        CP_ASYNC16(_d, _s); \
    } \
    CP_COMMIT(); \
} while (0)

__global__ void __launch_bounds__(256, 2) gemm_mma2(
    const u16* __restrict__ Ah, const u16* __restrict__ Al,
    const u16* __restrict__ Wh, const u16* __restrict__ Wl,
    const float* __restrict__ bias,
    float* __restrict__ Cf, u16* __restrict__ C16,
    int mode, float scale)
{
    extern __shared__ char gsm[];
    const unsigned sbase = smem_u32(gsm);
    const int tid  = threadIdx.x;
    const int lane = tid & 31;
    const int warp = tid >> 5;
    const int warp_m = warp & 1, warp_n = warp >> 1;
    const int bn = blockIdx.x, bm = blockIdx.y;

    const u16* srcs[4];
    srcs[0] = Ah + (size_t)(bm * 128) * DM;
    srcs[1] = Al + (size_t)(bm * 128) * DM;
    srcs[2] = Wh + (size_t)(bn * 128) * DM;
    srcs[3] = Wl + (size_t)(bn * 128) * DM;

    const int trow = tid >> 2;
    const int tc16 = tid & 3;

    float acc[4][4][4];
#pragma unroll
    for (int i = 0; i < 4; i++)
#pragma unroll
        for (int j = 0; j < 4; j++)
#pragma unroll
            for (int t = 0; t < 4; t++) acc[i][j][t] = 0.f;

    const unsigned OFF_AH = 0, OFF_AL = 10240, OFF_WH = 20480, OFF_WL = 30720;
    const unsigned a_row = warp_m*64 + (lane & 15);
    const unsigned a_kof = (lane >> 4) * 8;
    const unsigned b_row = warp_n*32 + (lane & 7) + ((lane & 16) >> 1);
    const unsigned b_kof = (lane & 8);

    GEMM_ISSUE(0, 0);

    const int NCHUNK = DM / 32;
    for (int c = 0; c < NCHUNK; c++) {
        CP_WAIT0();
        __syncthreads();
        if (c + 1 < NCHUNK) GEMM_ISSUE(c + 1, (c + 1) & 1);

        const unsigned st = sbase + (unsigned)(c & 1) * STAGE_B;
#pragma unroll
        for (int ks = 0; ks < 2; ks++) {
            const unsigned kbyte = (unsigned)(ks * 16) * 2;
            u32 bh[8], bl[8];
#pragma unroll
            for (int jp = 0; jp < 2; jp++) {
                unsigned roff = (b_row + jp*16) * (GP*2) + kbyte + b_kof*2;
                ldsm4(bh[jp*4+0], bh[jp*4+1], bh[jp*4+2], bh[jp*4+3],
                      st + OFF_WH + roff);
                ldsm4(bl[jp*4+0], bl[jp*4+1], bl[jp*4+2], bl[jp*4+3],
                      st + OFF_WL + roff);
            }
#pragma unroll
            for (int i = 0; i < 4; i++) {
                unsigned roff = (a_row + i*16) * (GP*2) + kbyte + a_kof*2;
                u32 ah[4], al[4];
                ldsm4(ah[0], ah[1], ah[2], ah[3], st + OFF_AH + roff);
                ldsm4(al[0], al[1], al[2], al[3], st + OFF_AL + roff);
#pragma unroll
                for (int j = 0; j < 4; j++) {
                    mma16816(acc[i][j], ah, &bh[j*2]);
                    mma16816(acc[i][j], ah, &bl[j*2]);
                    mma16816(acc[i][j], al, &bh[j*2]);
                }
            }
        }
        __syncthreads();
    }

    const int gid = lane >> 2, tig = lane & 3;
#pragma unroll
    for (int i = 0; i < 4; i++) {
#pragma unroll
        for (int j = 0; j < 4; j++) {
            int gnc = bn*128 + warp_n*32 + j*8 + tig*2;
            float2 bv = *(const float2*)(bias + gnc);
#pragma unroll
            for (int half = 0; half < 2; half++) {
                int m = bm*128 + warp_m*64 + i*16 + gid + half*8;
                float o0 = (acc[i][j][half*2+0] + bv.x) * scale;
                float o1 = (acc[i][j][half*2+1] + bv.y) * scale;
                if (mode == 0) {
                    *(float2*)(Cf + (size_t)m * DM + gnc) = make_float2(o0, o1);
                } else {
                    // fp16 head plane [B,H,S,64]
                    int bi = m >> 11, s = m & (SEQ - 1);
                    int hh = gnc >> 6, d = gnc & 63;
                    size_t idx = (((size_t)(bi*NH + hh) * SEQ + s) << 6) + d;
                    *(u32*)(C16 + idx) = packh2(o0, o1);
                }
            }
        }
    }
}

// ---------------- attention: all-fp16 MMA, static-shift softmax ----------
// smem: Q [128][72] fp16 @0 (18432B); buf{0,1}: K 64x144 @+0, V @+9216.
#define AQ 0
#define ABUF0 18432
#define ABUF1 36864
#define ASMEM_BYTES 55296

__global__ void __launch_bounds__(256, 2) attn_mma_kernel(
    const u16* __restrict__ Qh, const u16* __restrict__ Kh,
    const u16* __restrict__ Vh,
    u16* __restrict__ Ch, u16* __restrict__ Cl)
{
    extern __shared__ char asm_[];
    const unsigned sbase = smem_u32(asm_);
    const int tid  = threadIdx.x;
    const int lane = tid & 31;
    const int w    = tid >> 5;
    const int gid  = lane >> 2, tig = lane & 3;
    const int qt = blockIdx.x, h = blockIdx.y, b = blockIdx.z;
    const size_t bh = (size_t)(b*NH + h) * SEQ;

    const int unit = tid >> 1;          // 0..127
    const int uhalf = tid & 1;          // 64B half of a 128B row

    // KV tile 0 (K rows = units 0..63, V rows = units 64..127)
    {
        const u16* pl = (unit < 64) ? Kh : Vh;
        int row = unit & 63;
        const u16* src = pl + ((bh + row) << 6) + uhalf*32;
        unsigned dst = sbase + ABUF0 + ((unit < 64) ? 0u : 9216u)
                     + row*144 + uhalf*64;
#pragma unroll
        for (int i = 0; i < 4; i++) CP_ASYNC16(dst + i*16, src + i*8);
    }
    // Q tile (128 rows)
    {
        const u16* src = Qh + ((bh + qt*128 + unit) << 6) + uhalf*32;
        unsigned dst = sbase + AQ + unit*144 + uhalf*64;
#pragma unroll
        for (int i = 0; i < 4; i++) CP_ASYNC16(dst + i*16, src + i*8);
    }
    CP_COMMIT();
    CP_WAIT0();
    __syncthreads();

    // preload Q frags (fp16, 16 regs)
    u32 qf[4][4];
    {
        unsigned rbase = (unsigned)(w*16 + (lane & 15)) * 144 + (lane >> 4) * 16;
#pragma unroll
        for (int ks = 0; ks < 4; ks++)
            ldsm4(qf[ks][0], qf[ks][1], qf[ks][2], qf[ks][3],
                  sbase + AQ + rbase + ks*32);
    }

    float o_[8][4];
#pragma unroll
    for (int j = 0; j < 8; j++)
#pragma unroll
        for (int t = 0; t < 4; t++) o_[j][t] = 0.f;
    float l0 = 0.f, l1 = 0.f;

    const unsigned b_rowoff = ((lane & 7) + ((lane & 16) >> 1)) * 144 + (lane & 8) * 2;
    const unsigned v_rowoff = (lane & 15) * 144 + (lane >> 4) * 16;

    for (int kt = 0; kt < SEQ/64; kt++) {
        const unsigned cbuf = (kt & 1) ? ABUF1 : ABUF0;

        if (kt + 1 < SEQ/64) {
            const u16* pl = (unit < 64) ? Kh : Vh;
            int row = unit & 63;
            const u16* src = pl + ((bh + (kt+1)*64 + row) << 6) + uhalf*32;
            unsigned dst = sbase + ((kt & 1) ? ABUF0 : ABUF1)
                         + ((unit < 64) ? 0u : 9216u) + row*144 + uhalf*64;
#pragma unroll
            for (int i = 0; i < 4; i++) CP_ASYNC16(dst + i*16, src + i*8);
            CP_COMMIT();
        }

        // ---- QK^T: 1 fp16 MMA per position (32 total), frag dbl-buffered ----
        float s_[8][4];
#pragma unroll
        for (int j = 0; j < 8; j++)
#pragma unroll
            for (int t = 0; t < 4; t++) s_[j][t] = 0.f;

        u32 kf2[2][4];
        ldsm4(kf2[0][0], kf2[0][1], kf2[0][2], kf2[0][3],
              sbase + cbuf + b_rowoff);
#pragma unroll
        for (int it = 0; it < 16; it++) {
            const int ks = it >> 2, ng = it & 3;
            const int cur = it & 1;
            if (it + 1 < 16) {
                const int ks2 = (it + 1) >> 2, ng2 = (it + 1) & 3;
                unsigned roff = (unsigned)(ng2*16)*144 + b_rowoff + ks2*32;
                ldsm4(kf2[cur^1][0], kf2[cur^1][1], kf2[cur^1][2], kf2[cur^1][3],
                      sbase + cbuf + roff);
            }
            mma16816h(s_[2*ng+0], qf[ks], &kf2[cur][0]);
            mma16816h(s_[2*ng+1], qf[ks], &kf2[cur][2]);
        }

        // ---- PV: P fp16 (RN), 1 MMA per position ----
        u32 vf2[2][4];
        ldsm4t(vf2[0][0], vf2[0][1], vf2[0][2], vf2[0][3],
               sbase + cbuf + 9216u + v_rowoff);
        u32 pa[4];
#pragma unroll
        for (int it = 0; it < 16; it++) {
            const int ks = it >> 2, ng = it & 3;
            const int cur = it & 1;
            if (it + 1 < 16) {
                const int ks2 = (it + 1) >> 2, ng2 = (it + 1) & 3;
                unsigned roff = (unsigned)(ks2*16)*144 + v_rowoff + (unsigned)(ng2*32);
                ldsm4t(vf2[cur^1][0], vf2[cur^1][1], vf2[cur^1][2], vf2[cur^1][3],
                       sbase + cbuf + 9216u + roff);
            }
            if (ng == 0) {
                float p0 = fexp(s_[2*ks+0][0]);
                float p1 = fexp(s_[2*ks+0][1]);
                float p2 = fexp(s_[2*ks+0][2]);
                float p3 = fexp(s_[2*ks+0][3]);
                float q0 = fexp(s_[2*ks+1][0]);
                float q1 = fexp(s_[2*ks+1][1]);
                float q2 = fexp(s_[2*ks+1][2]);
                float q3 = fexp(s_[2*ks+1][3]);
                l0 += (p0 + p1) + (q0 + q1);
                l1 += (p2 + p3) + (q2 + q3);
                pa[0] = packh2(p0, p1);
                pa[1] = packh2(p2, p3);
                pa[2] = packh2(q0, q1);
                pa[3] = packh2(q2, q3);
            }
            mma16816h(o_[2*ng+0], pa, &vf2[cur][0]);
            mma16816h(o_[2*ng+1], pa, &vf2[cur][2]);
        }

        CP_WAIT0();
        __syncthreads();
    }

    l0 += __shfl_xor_sync(0xffffffffu, l0, 1);
    l0 += __shfl_xor_sync(0xffffffffu, l0, 2);
    l1 += __shfl_xor_sync(0xffffffffu, l1, 1);
    l1 += __shfl_xor_sync(0xffffffffu, l1, 2);

    float inv0 = 1.f / l0, inv1 = 1.f / l1;
    int r0 = qt*128 + w*16 + gid;
    size_t base0 = ((size_t)(b*SEQ) + r0) * DM + h*64;
    size_t base1 = base0 + (size_t)8 * DM;
#pragma unroll
    for (int j = 0; j < 8; j++) {
        int d = j*8 + tig*2;
        float a0 = o_[j][0] * inv0, a1 = o_[j][1] * inv0;
        float h0 = truncbf(a0), h1 = truncbf(a1);
        *(u32*)(Ch + base0 + d) = packbf(h0, h1);
        *(u32*)(Cl + base0 + d) = packbf(a0 - h0, a1 - h1);
        float c0 = o_[j][2] * inv1, c1 = o_[j][3] * inv1;
        float g0 = truncbf(c0), g1 = truncbf(c1);
        *(u32*)(Ch + base1 + d) = packbf(g0, g1);
        *(u32*)(Cl + base1 + d) = packbf(c0 - g0, c1 - g1);
    }
}

// ---------------- launch ----------------
extern "C" void kernel_launch(void* const* d_in, const int* in_sizes, int n_in,
                              void* d_out, int out_size)
{
    const float* q    = (const float*)d_in[0];
    const float* k    = (const float*)d_in[1];
    const float* v    = (const float*)d_in[2];
    const float* wq_w = (const float*)d_in[3];
    const float* wq_b = (const float*)d_in[4];
    const float* wk_w = (const float*)d_in[5];
    const float* wk_b = (const float*)d_in[6];
    const float* wv_w = (const float*)d_in[7];
    const float* wv_b = (const float*)d_in[8];
    const float* wo_w = (const float*)d_in[9];
    const float* wo_b = (const float*)d_in[10];
    float* out = (float*)d_out;

    u16 *ah, *al, *wh0, *wl0, *q16, *k16, *v16, *ch, *cl;
    cudaGetSymbolAddress((void**)&ah,  g_ah);
    cudaGetSymbolAddress((void**)&al,  g_al);
    cudaGetSymbolAddress((void**)&wh0, g_w_h);
    cudaGetSymbolAddress((void**)&wl0, g_w_l);
    cudaGetSymbolAddress((void**)&q16, g_q16);
    cudaGetSymbolAddress((void**)&k16, g_k16);
    cudaGetSymbolAddress((void**)&v16, g_v16);
    cudaGetSymbolAddress((void**)&ch,  g_ch);
    cudaGetSymbolAddress((void**)&cl,  g_cl);
    const size_t WSZ = (size_t)DM * DM;

    cudaFuncSetAttribute(gemm_mma2,
                         cudaFuncAttributeMaxDynamicSharedMemorySize, GSMEM_BYTES);
    cudaFuncSetAttribute(attn_mma_kernel,
                         cudaFuncAttributeMaxDynamicSharedMemorySize, ASMEM_BYTES);

    const int nW4 = DM*DM/4, nA4 = MROWS*DM/4;
    const int cblk = 256;
    const int cgW = (nW4 + cblk - 1) / cblk;
    const int cgA = (nA4 + cblk - 1) / cblk;

    conv_split<<<cgW, cblk>>>((const float4*)wq_w, (uint2*)(wh0 + 0*WSZ), (uint2*)(wl0 + 0*WSZ), nW4);
    conv_split<<<cgW, cblk>>>((const float4*)wk_w, (uint2*)(wh0 + 1*WSZ), (uint2*)(wl0 + 1*WSZ), nW4);
    conv_split<<<cgW, cblk>>>((const float4*)wv_w, (uint2*)(wh0 + 2*WSZ), (uint2*)(wl0 + 2*WSZ), nW4);
    conv_split<<<cgW, cblk>>>((const float4*)wo_w, (uint2*)(wh0 + 3*WSZ), (uint2*)(wl0 + 3*WSZ), nW4);

    dim3 gblk(256), ggrid(DM/128, MROWS/128);

    conv_split<<<cgA, cblk>>>((const float4*)q, (uint2*)ah, (uint2*)al, nA4);
    gemm_mma2<<<ggrid, gblk, GSMEM_BYTES>>>(ah, al, wh0 + 0*WSZ, wl0 + 0*WSZ,
                                            wq_b, nullptr, q16, 1, 0.125f);
    conv_split<<<cgA, cblk>>>((const float4*)k, (uint2*)ah, (uint2*)al, nA4);
    gemm_mma2<<<ggrid, gblk, GSMEM_BYTES>>>(ah, al, wh0 + 1*WSZ, wl0 + 1*WSZ,
                                            wk_b, nullptr, k16, 1, 1.0f);
    conv_split<<<cgA, cblk>>>((const float4*)v, (uint2*)ah, (uint2*)al, nA4);
    gemm_mma2<<<ggrid, gblk, GSMEM_BYTES>>>(ah, al, wh0 + 2*WSZ, wl0 + 2*WSZ,
                                            wv_b, nullptr, v16, 1, 1.0f);

    dim3 ablk(256), agrid(SEQ/128, NH, NB);
    attn_mma_kernel<<<agrid, ablk, ASMEM_BYTES>>>(q16, k16, v16, ch, cl);

    gemm_mma2<<<ggrid, gblk, GSMEM_BYTES>>>(ch, cl, wh0 + 3*WSZ, wl0 + 3*WSZ,
                                            wo_b, out, nullptr, 0, 1.0f);
}

// round 12
// speedup vs baseline: 1.9285x; 1.3036x over previous
#include <cuda_runtime.h>
#include <cuda_fp16.h>
#include <cstdint>

#define NB   4
#define SEQ  2048
#define NH   16
#define DEP  64
#define DM   1024
#define MROWS (NB*SEQ)

typedef unsigned short u16;
typedef unsigned int   u32;

// ---------------- scratch ----------------
__device__ u16 g_a16[(size_t)MROWS*DM];          // input fp16 plane (reused)
__device__ u16 g_w_h[4][(size_t)DM*DM];          // weights fp16 hi
__device__ u16 g_w_l[4][(size_t)DM*DM];          // weights fp16 residual
__device__ u16 g_q16[(size_t)MROWS*DM];          // fp16 head planes [B,H,S,64]
__device__ u16 g_k16[(size_t)MROWS*DM];
__device__ u16 g_v16[(size_t)MROWS*DM];
__device__ u16 g_c16[(size_t)MROWS*DM];          // ctx fp16 [B,S,DM]

// ---------------- helpers ----------------
__device__ __forceinline__ unsigned smem_u32(const void* p) {
    unsigned r;
    asm("{ .reg .u64 t; cvta.to.shared.u64 t, %1; cvt.u32.u64 %0, t; }"
        : "=r"(r) : "l"(p));
    return r;
}

__device__ __forceinline__ void ldsm4(u32& r0, u32& r1, u32& r2, u32& r3,
                                      unsigned addr) {
    asm volatile("ldmatrix.sync.aligned.m8n8.x4.shared.b16 {%0,%1,%2,%3}, [%4];"
                 : "=r"(r0), "=r"(r1), "=r"(r2), "=r"(r3) : "r"(addr));
}
__device__ __forceinline__ void ldsm4t(u32& r0, u32& r1, u32& r2, u32& r3,
                                       unsigned addr) {
    asm volatile("ldmatrix.sync.aligned.m8n8.x4.trans.shared.b16 {%0,%1,%2,%3}, [%4];"
                 : "=r"(r0), "=r"(r1), "=r"(r2), "=r"(r3) : "r"(addr));
}
// fp16 mma
__device__ __forceinline__ void mma16816h(float* d, const u32* a, const u32* b) {
    asm volatile("mma.sync.aligned.m16n8k16.row.col.f32.f16.f16.f32 "
                 "{%0,%1,%2,%3}, {%4,%5,%6,%7}, {%8,%9}, {%0,%1,%2,%3};"
                 : "+f"(d[0]), "+f"(d[1]), "+f"(d[2]), "+f"(d[3])
                 : "r"(a[0]), "r"(a[1]), "r"(a[2]), "r"(a[3]),
                   "r"(b[0]), "r"(b[1]));
}

#define CP_ASYNC16(dst, src) \
    asm volatile("cp.async.cg.shared.global [%0], [%1], 16;" :: "r"(dst), "l"(src))
#define CP_COMMIT() asm volatile("cp.async.commit_group;" ::: "memory")
#define CP_WAIT0()  asm volatile("cp.async.wait_group 0;" ::: "memory")

// 2^x via MUFU (exp folded: q pre-scaled by 0.125*log2e)
__device__ __forceinline__ float fex2(float x) {
    float r; asm("ex2.approx.f32 %0, %1;" : "=f"(r) : "f"(x)); return r;
}

// pack two fp32 -> fp16x2 (RN): lo = a, hi = b
__device__ __forceinline__ u32 packh2(float a, float b) {
    u32 d; asm("cvt.rn.f16x2.f32 %0, %1, %2;" : "=r"(d) : "f"(b), "f"(a));
    return d;
}
// fp16 (as low 16 bits) -> fp32
__device__ __forceinline__ float h2f(u32 hbits) {
    float f; asm("{ .reg .b16 t; mov.b16 t, %1; cvt.f32.f16 %0, t; }"
                 : "=f"(f) : "h"((unsigned short)hbits));
    return f;
}

// ---------------- conversions ----------------
// fp32 -> single fp16 plane
__global__ void conv_a16(const float4* __restrict__ src,
                         uint2* __restrict__ out, int n4)
{
    int i = blockIdx.x * blockDim.x + threadIdx.x;
    if (i >= n4) return;
    float4 v = src[i];
    out[i] = make_uint2(packh2(v.x, v.y), packh2(v.z, v.w));
}
// fp32 -> fp16 hi + fp16 residual planes
__global__ void conv_w16(const float4* __restrict__ src,
                         uint2* __restrict__ hi, uint2* __restrict__ lo, int n4)
{
    int i = blockIdx.x * blockDim.x + threadIdx.x;
    if (i >= n4) return;
    float4 v = src[i];
    u32 p01 = packh2(v.x, v.y);
    u32 p23 = packh2(v.z, v.w);
    float h0 = h2f(p01 & 0xffffu), h1 = h2f(p01 >> 16);
    float h2 = h2f(p23 & 0xffffu), h3 = h2f(p23 >> 16);
    hi[i] = make_uint2(p01, p23);
    lo[i] = make_uint2(packh2(v.x - h0, v.y - h1), packh2(v.z - h2, v.w - h3));
}

// ---------------- GEMM: C = A @ W^T + bias (A fp16, W fp16 hi/lo, 2 MMA) ---
#define GP 40
#define STAGE_B 30720
#define GSMEM_BYTES (2*STAGE_B)

#define GEMM_ISSUE(chunk, stage) do { \
    unsigned _db = sbase + (stage)*STAGE_B; \
    int _ck = (chunk) * 32; \
    _Pragma("unroll") \
    for (int _i = 0; _i < 6; _i++) { \
        int _pl = _i >> 1; \
        int _row = ((_i & 1) << 6) + trow; \
        const u16* _s = srcs[_pl] + (size_t)_row * DM + _ck + tc16 * 8; \
        unsigned _d = _db + _pl * 10240 + _row * 80 + tc16 * 16; \
        CP_ASYNC16(_d, _s); \
    } \
    CP_COMMIT(); \
} while (0)

__global__ void __launch_bounds__(256, 2) gemm_mma2(
    const u16* __restrict__ A16,
    const u16* __restrict__ Wh, const u16* __restrict__ Wl,
    const float* __restrict__ bias,
    float* __restrict__ Cf, u16* __restrict__ C16,
    int mode, float scale)
{
    extern __shared__ char gsm[];
    const unsigned sbase = smem_u32(gsm);
    const int tid  = threadIdx.x;
    const int lane = tid & 31;
    const int warp = tid >> 5;
    const int warp_m = warp & 1, warp_n = warp >> 1;
    const int bn = blockIdx.x, bm = blockIdx.y;

    const u16* srcs[3];
    srcs[0] = A16 + (size_t)(bm * 128) * DM;
    srcs[1] = Wh  + (size_t)(bn * 128) * DM;
    srcs[2] = Wl  + (size_t)(bn * 128) * DM;

    const int trow = tid >> 2;
    const int tc16 = tid & 3;

    float acc[4][4][4];
#pragma unroll
    for (int i = 0; i < 4; i++)
#pragma unroll
        for (int j = 0; j < 4; j++)
#pragma unroll
            for (int t = 0; t < 4; t++) acc[i][j][t] = 0.f;

    const unsigned OFF_A = 0, OFF_WH = 10240, OFF_WL = 20480;
    const unsigned a_row = warp_m*64 + (lane & 15);
    const unsigned a_kof = (lane >> 4) * 8;
    const unsigned b_row = warp_n*32 + (lane & 7) + ((lane & 16) >> 1);
    const unsigned b_kof = (lane & 8);

    GEMM_ISSUE(0, 0);

    const int NCHUNK = DM / 32;
    for (int c = 0; c < NCHUNK; c++) {
        CP_WAIT0();
        __syncthreads();
        if (c + 1 < NCHUNK) GEMM_ISSUE(c + 1, (c + 1) & 1);

        const unsigned st = sbase + (unsigned)(c & 1) * STAGE_B;
#pragma unroll
        for (int ks = 0; ks < 2; ks++) {
            const unsigned kbyte = (unsigned)(ks * 16) * 2;
            u32 bh[8], bl[8];
#pragma unroll
            for (int jp = 0; jp < 2; jp++) {
                unsigned roff = (b_row + jp*16) * (GP*2) + kbyte + b_kof*2;
                ldsm4(bh[jp*4+0], bh[jp*4+1], bh[jp*4+2], bh[jp*4+3],
                      st + OFF_WH + roff);
                ldsm4(bl[jp*4+0], bl[jp*4+1], bl[jp*4+2], bl[jp*4+3],
                      st + OFF_WL + roff);
            }
#pragma unroll
            for (int i = 0; i < 4; i++) {
                unsigned roff = (a_row + i*16) * (GP*2) + kbyte + a_kof*2;
                u32 ah[4];
                ldsm4(ah[0], ah[1], ah[2], ah[3], st + OFF_A + roff);
#pragma unroll
                for (int j = 0; j < 4; j++) {
                    mma16816h(acc[i][j], ah, &bh[j*2]);
                    mma16816h(acc[i][j], ah, &bl[j*2]);
                }
            }
        }
        __syncthreads();
    }

    const int gid = lane >> 2, tig = lane & 3;
#pragma unroll
    for (int i = 0; i < 4; i++) {
#pragma unroll
        for (int j = 0; j < 4; j++) {
            int gnc = bn*128 + warp_n*32 + j*8 + tig*2;
            float2 bv = *(const float2*)(bias + gnc);
#pragma unroll
            for (int half = 0; half < 2; half++) {
                int m = bm*128 + warp_m*64 + i*16 + gid + half*8;
                float o0 = (acc[i][j][half*2+0] + bv.x) * scale;
                float o1 = (acc[i][j][half*2+1] + bv.y) * scale;
                if (mode == 0) {
                    *(float2*)(Cf + (size_t)m * DM + gnc) = make_float2(o0, o1);
                } else {
                    // fp16 head plane [B,H,S,64]
                    int bi = m >> 11, s = m & (SEQ - 1);
                    int hh = gnc >> 6, d = gnc & 63;
                    size_t idx = (((size_t)(bi*NH + hh) * SEQ + s) << 6) + d;
                    *(u32*)(C16 + idx) = packh2(o0, o1);
                }
            }
        }
    }
}

// ---------------- attention: fp16 MMA, MUFU softmax (log2e pre-folded) ----
#define AQ 0
#define ABUF0 18432
#define ABUF1 36864
#define ASMEM_BYTES 55296

__global__ void __launch_bounds__(256, 2) attn_mma_kernel(
    const u16* __restrict__ Qh, const u16* __restrict__ Kh,
    const u16* __restrict__ Vh, u16* __restrict__ C16)
{
    extern __shared__ char asm_[];
    const unsigned sbase = smem_u32(asm_);
    const int tid  = threadIdx.x;
    const int lane = tid & 31;
    const int w    = tid >> 5;
    const int gid  = lane >> 2, tig = lane & 3;
    const int qt = blockIdx.x, h = blockIdx.y, b = blockIdx.z;
    const size_t bh = (size_t)(b*NH + h) * SEQ;

    const int unit = tid >> 1;
    const int uhalf = tid & 1;

    // KV tile 0
    {
        const u16* pl = (unit < 64) ? Kh : Vh;
        int row = unit & 63;
        const u16* src = pl + ((bh + row) << 6) + uhalf*32;
        unsigned dst = sbase + ABUF0 + ((unit < 64) ? 0u : 9216u)
                     + row*144 + uhalf*64;
#pragma unroll
        for (int i = 0; i < 4; i++) CP_ASYNC16(dst + i*16, src + i*8);
    }
    // Q tile
    {
        const u16* src = Qh + ((bh + qt*128 + unit) << 6) + uhalf*32;
        unsigned dst = sbase + AQ + unit*144 + uhalf*64;
#pragma unroll
        for (int i = 0; i < 4; i++) CP_ASYNC16(dst + i*16, src + i*8);
    }
    CP_COMMIT();
    CP_WAIT0();
    __syncthreads();

    u32 qf[4][4];
    {
        unsigned rbase = (unsigned)(w*16 + (lane & 15)) * 144 + (lane >> 4) * 16;
#pragma unroll
        for (int ks = 0; ks < 4; ks++)
            ldsm4(qf[ks][0], qf[ks][1], qf[ks][2], qf[ks][3],
                  sbase + AQ + rbase + ks*32);
    }

    float o_[8][4];
#pragma unroll
    for (int j = 0; j < 8; j++)
#pragma unroll
        for (int t = 0; t < 4; t++) o_[j][t] = 0.f;
    float l0 = 0.f, l1 = 0.f;

    const unsigned b_rowoff = ((lane & 7) + ((lane & 16) >> 1)) * 144 + (lane & 8) * 2;
    const unsigned v_rowoff = (lane & 15) * 144 + (lane >> 4) * 16;

    for (int kt = 0; kt < SEQ/64; kt++) {
        const unsigned cbuf = (kt & 1) ? ABUF1 : ABUF0;

        if (kt + 1 < SEQ/64) {
            const u16* pl = (unit < 64) ? Kh : Vh;
            int row = unit & 63;
            const u16* src = pl + ((bh + (kt+1)*64 + row) << 6) + uhalf*32;
            unsigned dst = sbase + ((kt & 1) ? ABUF0 : ABUF1)
                         + ((unit < 64) ? 0u : 9216u) + row*144 + uhalf*64;
#pragma unroll
            for (int i = 0; i < 4; i++) CP_ASYNC16(dst + i*16, src + i*8);
            CP_COMMIT();
        }

        // ---- QK^T (1 MMA per position) ----
        float s_[8][4];
#pragma unroll
        for (int j = 0; j < 8; j++)
#pragma unroll
            for (int t = 0; t < 4; t++) s_[j][t] = 0.f;

        u32 kf2[2][4];
        ldsm4(kf2[0][0], kf2[0][1], kf2[0][2], kf2[0][3],
              sbase + cbuf + b_rowoff);
#pragma unroll
        for (int it = 0; it < 16; it++) {
            const int ks = it >> 2, ng = it & 3;
            const int cur = it & 1;
            if (it + 1 < 16) {
                const int ks2 = (it + 1) >> 2, ng2 = (it + 1) & 3;
                unsigned roff = (unsigned)(ng2*16)*144 + b_rowoff + ks2*32;
                ldsm4(kf2[cur^1][0], kf2[cur^1][1], kf2[cur^1][2], kf2[cur^1][3],
                      sbase + cbuf + roff);
            }
            mma16816h(s_[2*ng+0], qf[ks], &kf2[cur][0]);
            mma16816h(s_[2*ng+1], qf[ks], &kf2[cur][2]);
        }

        // ---- p = 2^s (MUFU); P fp16; PV ----
        u32 vf2[2][4];
        ldsm4t(vf2[0][0], vf2[0][1], vf2[0][2], vf2[0][3],
               sbase + cbuf + 9216u + v_rowoff);
        u32 pa[4];
#pragma unroll
        for (int it = 0; it < 16; it++) {
            const int ks = it >> 2, ng = it & 3;
            const int cur = it & 1;
            if (it + 1 < 16) {
                const int ks2 = (it + 1) >> 2, ng2 = (it + 1) & 3;
                unsigned roff = (unsigned)(ks2*16)*144 + v_rowoff + (unsigned)(ng2*32);
                ldsm4t(vf2[cur^1][0], vf2[cur^1][1], vf2[cur^1][2], vf2[cur^1][3],
                       sbase + cbuf + 9216u + roff);
            }
            if (ng == 0) {
                float p0 = fex2(s_[2*ks+0][0]);
                float p1 = fex2(s_[2*ks+0][1]);
                float p2 = fex2(s_[2*ks+0][2]);
                float p3 = fex2(s_[2*ks+0][3]);
                float q0 = fex2(s_[2*ks+1][0]);
                float q1 = fex2(s_[2*ks+1][1]);
                float q2 = fex2(s_[2*ks+1][2]);
                float q3 = fex2(s_[2*ks+1][3]);
                l0 += (p0 + p1) + (q0 + q1);
                l1 += (p2 + p3) + (q2 + q3);
                pa[0] = packh2(p0, p1);
                pa[1] = packh2(p2, p3);
                pa[2] = packh2(q0, q1);
                pa[3] = packh2(q2, q3);
            }
            mma16816h(o_[2*ng+0], pa, &vf2[cur][0]);
            mma16816h(o_[2*ng+1], pa, &vf2[cur][2]);
        }

        CP_WAIT0();
        __syncthreads();
    }

    l0 += __shfl_xor_sync(0xffffffffu, l0, 1);
    l0 += __shfl_xor_sync(0xffffffffu, l0, 2);
    l1 += __shfl_xor_sync(0xffffffffu, l1, 1);
    l1 += __shfl_xor_sync(0xffffffffu, l1, 2);

    float inv0 = 1.f / l0, inv1 = 1.f / l1;
    int r0 = qt*128 + w*16 + gid;
    size_t base0 = ((size_t)(b*SEQ) + r0) * DM + h*64;
    size_t base1 = base0 + (size_t)8 * DM;
#pragma unroll
    for (int j = 0; j < 8; j++) {
        int d = j*8 + tig*2;
        *(u32*)(C16 + base0 + d) = packh2(o_[j][0]*inv0, o_[j][1]*inv0);
        *(u32*)(C16 + base1 + d) = packh2(o_[j][2]*inv1, o_[j][3]*inv1);
    }
}

// ---------------- launch ----------------
extern "C" void kernel_launch(void* const* d_in, const int* in_sizes, int n_in,
                              void* d_out, int out_size)
{
    const float* q    = (const float*)d_in[0];
    const float* k    = (const float*)d_in[1];
    const float* v    = (const float*)d_in[2];
    const float* wq_w = (const float*)d_in[3];
    const float* wq_b = (const float*)d_in[4];
    const float* wk_w = (const float*)d_in[5];
    const float* wk_b = (const float*)d_in[6];
    const float* wv_w = (const float*)d_in[7];
    const float* wv_b = (const float*)d_in[8];
    const float* wo_w = (const float*)d_in[9];
    const float* wo_b = (const float*)d_in[10];
    float* out = (float*)d_out;

    u16 *a16, *wh0, *wl0, *q16, *k16, *v16, *c16;
    cudaGetSymbolAddress((void**)&a16, g_a16);
    cudaGetSymbolAddress((void**)&wh0, g_w_h);
    cudaGetSymbolAddress((void**)&wl0, g_w_l);
    cudaGetSymbolAddress((void**)&q16, g_q16);
    cudaGetSymbolAddress((void**)&k16, g_k16);
    cudaGetSymbolAddress((void**)&v16, g_v16);
    cudaGetSymbolAddress((void**)&c16, g_c16);
    const size_t WSZ = (size_t)DM * DM;

    cudaFuncSetAttribute(gemm_mma2,
                         cudaFuncAttributeMaxDynamicSharedMemorySize, GSMEM_BYTES);
    cudaFuncSetAttribute(attn_mma_kernel,
                         cudaFuncAttributeMaxDynamicSharedMemorySize, ASMEM_BYTES);

    const int nW4 = DM*DM/4, nA4 = MROWS*DM/4;
    const int cblk = 256;
    const int cgW = (nW4 + cblk - 1) / cblk;
    const int cgA = (nA4 + cblk - 1) / cblk;

    conv_w16<<<cgW, cblk>>>((const float4*)wq_w, (uint2*)(wh0 + 0*WSZ), (uint2*)(wl0 + 0*WSZ), nW4);
    conv_w16<<<cgW, cblk>>>((const float4*)wk_w, (uint2*)(wh0 + 1*WSZ), (uint2*)(wl0 + 1*WSZ), nW4);
    conv_w16<<<cgW, cblk>>>((const float4*)wv_w, (uint2*)(wh0 + 2*WSZ), (uint2*)(wl0 + 2*WSZ), nW4);
    conv_w16<<<cgW, cblk>>>((const float4*)wo_w, (uint2*)(wh0 + 3*WSZ), (uint2*)(wl0 + 3*WSZ), nW4);

    dim3 gblk(256), ggrid(DM/128, MROWS/128);

    // Q projection: fold softmax scale AND log2e (for ex2) into epilogue
    const float QSCALE = 0.125f * 1.4426950408889634f;
    conv_a16<<<cgA, cblk>>>((const float4*)q, (uint2*)a16, nA4);
    gemm_mma2<<<ggrid, gblk, GSMEM_BYTES>>>(a16, wh0 + 0*WSZ, wl0 + 0*WSZ,
                                            wq_b, nullptr, q16, 1, QSCALE);
    conv_a16<<<cgA, cblk>>>((const float4*)k, (uint2*)a16, nA4);
    gemm_mma2<<<ggrid, gblk, GSMEM_BYTES>>>(a16, wh0 + 1*WSZ, wl0 + 1*WSZ,
                                            wk_b, nullptr, k16, 1, 1.0f);
    conv_a16<<<cgA, cblk>>>((const float4*)v, (uint2*)a16, nA4);
    gemm_mma2<<<ggrid, gblk, GSMEM_BYTES>>>(a16, wh0 + 2*WSZ, wl0 + 2*WSZ,
                                            wv_b, nullptr, v16, 1, 1.0f);

    dim3 ablk(256), agrid(SEQ/128, NH, NB);
    attn_mma_kernel<<<agrid, ablk, ASMEM_BYTES>>>(q16, k16, v16, c16);

    gemm_mma2<<<ggrid, gblk, GSMEM_BYTES>>>(c16, wh0 + 3*WSZ, wl0 + 3*WSZ,
                                            wo_b, out, nullptr, 0, 1.0f);
}

// round 13
// speedup vs baseline: 2.1006x; 1.0892x over previous
#include <cuda_runtime.h>
#include <cuda_fp16.h>
#include <cstdint>

#define NB   4
#define SEQ  2048
#define NH   16
#define DEP  64
#define DM   1024
#define MROWS (NB*SEQ)

typedef unsigned short u16;
typedef unsigned int   u32;

// ---------------- scratch ----------------
__device__ u16 g_w_h[4][(size_t)DM*DM];          // weights fp16 hi
__device__ u16 g_w_l[4][(size_t)DM*DM];          // weights fp16 residual
__device__ u16 g_q16[(size_t)MROWS*DM];          // fp16 head planes [B,H,S,64]
__device__ u16 g_k16[(size_t)MROWS*DM];
__device__ u16 g_v16[(size_t)MROWS*DM];
__device__ u16 g_c16[(size_t)MROWS*DM];          // ctx fp16 [B,S,DM]

// ---------------- helpers ----------------
__device__ __forceinline__ unsigned smem_u32(const void* p) {
    unsigned r;
    asm("{ .reg .u64 t; cvta.to.shared.u64 t, %1; cvt.u32.u64 %0, t; }"
        : "=r"(r) : "l"(p));
    return r;
}

__device__ __forceinline__ void ldsm4(u32& r0, u32& r1, u32& r2, u32& r3,
                                      unsigned addr) {
    asm volatile("ldmatrix.sync.aligned.m8n8.x4.shared.b16 {%0,%1,%2,%3}, [%4];"
                 : "=r"(r0), "=r"(r1), "=r"(r2), "=r"(r3) : "r"(addr));
}
__device__ __forceinline__ void ldsm4t(u32& r0, u32& r1, u32& r2, u32& r3,
                                       unsigned addr) {
    asm volatile("ldmatrix.sync.aligned.m8n8.x4.trans.shared.b16 {%0,%1,%2,%3}, [%4];"
                 : "=r"(r0), "=r"(r1), "=r"(r2), "=r"(r3) : "r"(addr));
}
// fp16 mma
__device__ __forceinline__ void mma16816h(float* d, const u32* a, const u32* b) {
    asm volatile("mma.sync.aligned.m16n8k16.row.col.f32.f16.f16.f32 "
                 "{%0,%1,%2,%3}, {%4,%5,%6,%7}, {%8,%9}, {%0,%1,%2,%3};"
                 : "+f"(d[0]), "+f"(d[1]), "+f"(d[2]), "+f"(d[3])
                 : "r"(a[0]), "r"(a[1]), "r"(a[2]), "r"(a[3]),
                   "r"(b[0]), "r"(b[1]));
}

#define CP_ASYNC16(dst, src) \
    asm volatile("cp.async.cg.shared.global [%0], [%1], 16;" :: "r"(dst), "l"(src))
#define CP_COMMIT() asm volatile("cp.async.commit_group;" ::: "memory")
#define CP_WAIT0()  asm volatile("cp.async.wait_group 0;" ::: "memory")

// 2^x via MUFU (exp folded: q pre-scaled by 0.125*log2e)
__device__ __forceinline__ float fex2(float x) {
    float r; asm("ex2.approx.f32 %0, %1;" : "=f"(r) : "f"(x)); return r;
}

// pack two fp32 -> fp16x2 (RN): lo = a, hi = b
__device__ __forceinline__ u32 packh2(float a, float b) {
    u32 d; asm("cvt.rn.f16x2.f32 %0, %1, %2;" : "=r"(d) : "f"(b), "f"(a));
    return d;
}
// fp16 (as low 16 bits) -> fp32
__device__ __forceinline__ float h2f(u32 hbits) {
    float f; asm("{ .reg .b16 t; mov.b16 t, %1; cvt.f32.f16 %0, t; }"
                 : "=f"(f) : "h"((unsigned short)hbits));
    return f;
}

// ---------------- weight conversion: fp32 -> fp16 hi + residual ----------
__global__ void conv_w16(const float4* __restrict__ src,
                         uint2* __restrict__ hi, uint2* __restrict__ lo, int n4)
{
    int i = blockIdx.x * blockDim.x + threadIdx.x;
    if (i >= n4) return;
    float4 v = src[i];
    u32 p01 = packh2(v.x, v.y);
    u32 p23 = packh2(v.z, v.w);
    float h0 = h2f(p01 & 0xffffu), h1 = h2f(p01 >> 16);
    float h2 = h2f(p23 & 0xffffu), h3 = h2f(p23 >> 16);
    hi[i] = make_uint2(p01, p23);
    lo[i] = make_uint2(packh2(v.x - h0, v.y - h1), packh2(v.z - h2, v.w - h3));
}

// ---------------- GEMM common geometry ----------------
// 128x128 tile, BK=32, 8 warps (2x4). Stage: A fp16 [128][40] + WH + WL.
#define GP 40
#define STAGE_B 30720
#define GSMEM_BYTES (2*STAGE_B)

// ---------------- fused QKV projection: fp32 A in, fp16 head planes out ---
// grid (8, 64, 3); z selects {q,k,v}. A converted fp32->fp16 in the loader.
__global__ void __launch_bounds__(256, 2) gemm_qkv(
    const float* __restrict__ Aq, const float* __restrict__ Ak,
    const float* __restrict__ Av,
    const u16* __restrict__ WhA, const u16* __restrict__ WlA,
    const float* __restrict__ bq, const float* __restrict__ bk,
    const float* __restrict__ bv,
    u16* __restrict__ Oq, u16* __restrict__ Ok, u16* __restrict__ Ov,
    float qscale)
{
    extern __shared__ char gsm[];
    const unsigned sbase = smem_u32(gsm);
    const int tid  = threadIdx.x;
    const int lane = tid & 31;
    const int warp = tid >> 5;
    const int warp_m = warp & 1, warp_n = warp >> 1;
    const int bn = blockIdx.x, bm = blockIdx.y, z = blockIdx.z;

    const float* A32 = ((z == 0) ? Aq : (z == 1) ? Ak : Av)
                     + (size_t)(bm * 128) * DM;
    const u16* Wh = WhA + (size_t)z * DM * DM + (size_t)(bn * 128) * DM;
    const u16* Wl = WlA + (size_t)z * DM * DM + (size_t)(bn * 128) * DM;
    const float* bias = (z == 0) ? bq : (z == 1) ? bk : bv;
    u16* C16 = (z == 0) ? Oq : (z == 1) ? Ok : Ov;
    const float scale = (z == 0) ? qscale : 1.0f;

    const int trow = tid >> 2;          // 0..63 (W loader)
    const int tc16 = tid & 3;
    const int arow = tid >> 3;          // 0..31 (A loader)
    const int af4  = tid & 7;

    float acc[4][4][4];
#pragma unroll
    for (int i = 0; i < 4; i++)
#pragma unroll
        for (int j = 0; j < 4; j++)
#pragma unroll
            for (int t = 0; t < 4; t++) acc[i][j][t] = 0.f;

    const unsigned OFF_A = 0, OFF_WH = 10240, OFF_WL = 20480;
    const unsigned a_row = warp_m*64 + (lane & 15);
    const unsigned a_kof = (lane >> 4) * 8;
    const unsigned b_row = warp_n*32 + (lane & 7) + ((lane & 16) >> 1);
    const unsigned b_kof = (lane & 8);

#define QKV_WISSUE(chunk, stage) do { \
    unsigned _db = sbase + (stage)*STAGE_B; \
    int _ck = (chunk) * 32; \
    _Pragma("unroll") \
    for (int _i = 0; _i < 4; _i++) { \
        int _pl = _i >> 1; \
        int _row = ((_i & 1) << 6) + trow; \
        const u16* _s = (_pl ? Wl : Wh) + (size_t)_row * DM + _ck + tc16 * 8; \
        unsigned _d = _db + OFF_WH + _pl * 10240 + _row * 80 + tc16 * 16; \
        CP_ASYNC16(_d, _s); \
    } \
    CP_COMMIT(); \
} while (0)

    float4 pa[4];
#define QKV_ALDG(chunk) do { \
    int _ck = (chunk) * 32; \
    _Pragma("unroll") \
    for (int _p = 0; _p < 4; _p++) { \
        int _row = _p*32 + arow; \
        pa[_p] = *(const float4*)(A32 + (size_t)_row * DM + _ck + af4*4); \
    } \
} while (0)

#define QKV_ASTS(stage) do { \
    char* _sp = gsm + (stage)*STAGE_B + OFF_A; \
    _Pragma("unroll") \
    for (int _p = 0; _p < 4; _p++) { \
        int _row = _p*32 + arow; \
        *(uint2*)(_sp + _row*80 + af4*8) = \
            make_uint2(packh2(pa[_p].x, pa[_p].y), packh2(pa[_p].z, pa[_p].w)); \
    } \
} while (0)

    QKV_WISSUE(0, 0);
    QKV_ALDG(0);

    const int NCHUNK = DM / 32;
    for (int c = 0; c < NCHUNK; c++) {
        const int st = c & 1;
        QKV_ASTS(st);
        CP_WAIT0();
        __syncthreads();
        if (c + 1 < NCHUNK) {
            QKV_WISSUE(c + 1, st ^ 1);
            QKV_ALDG(c + 1);
        }

        const unsigned sb = sbase + (unsigned)st * STAGE_B;
#pragma unroll
        for (int ks = 0; ks < 2; ks++) {
            const unsigned kbyte = (unsigned)(ks * 16) * 2;
            u32 bh[8], bl[8];
#pragma unroll
            for (int jp = 0; jp < 2; jp++) {
                unsigned roff = (b_row + jp*16) * (GP*2) + kbyte + b_kof*2;
                ldsm4(bh[jp*4+0], bh[jp*4+1], bh[jp*4+2], bh[jp*4+3],
                      sb + OFF_WH + roff);
                ldsm4(bl[jp*4+0], bl[jp*4+1], bl[jp*4+2], bl[jp*4+3],
                      sb + OFF_WL + roff);
            }
#pragma unroll
            for (int i = 0; i < 4; i++) {
                unsigned roff = (a_row + i*16) * (GP*2) + kbyte + a_kof*2;
                u32 ah[4];
                ldsm4(ah[0], ah[1], ah[2], ah[3], sb + OFF_A + roff);
#pragma unroll
                for (int j = 0; j < 4; j++) {
                    mma16816h(acc[i][j], ah, &bh[j*2]);
                    mma16816h(acc[i][j], ah, &bl[j*2]);
                }
            }
        }
        __syncthreads();
    }

    // epilogue: fp16 head plane [B,H,S,64]
    const int gid = lane >> 2, tig = lane & 3;
#pragma unroll
    for (int i = 0; i < 4; i++) {
#pragma unroll
        for (int j = 0; j < 4; j++) {
            int gnc = bn*128 + warp_n*32 + j*8 + tig*2;
            float2 bv = *(const float2*)(bias + gnc);
#pragma unroll
            for (int half = 0; half < 2; half++) {
                int m = bm*128 + warp_m*64 + i*16 + gid + half*8;
                float o0 = (acc[i][j][half*2+0] + bv.x) * scale;
                float o1 = (acc[i][j][half*2+1] + bv.y) * scale;
                int bi = m >> 11, s = m & (SEQ - 1);
                int hh = gnc >> 6, d = gnc & 63;
                size_t idx = (((size_t)(bi*NH + hh) * SEQ + s) << 6) + d;
                *(u32*)(C16 + idx) = packh2(o0, o1);
            }
        }
    }
}

// ---------------- output GEMM: fp16 A via cp.async, fp32 out ----------
#define GEMM_ISSUE(chunk, stage) do { \
    unsigned _db = sbase + (stage)*STAGE_B; \
    int _ck = (chunk) * 32; \
    _Pragma("unroll") \
    for (int _i = 0; _i < 6; _i++) { \
        int _pl = _i >> 1; \
        int _row = ((_i & 1) << 6) + trow; \
        const u16* _s = srcs[_pl] + (size_t)_row * DM + _ck + tc16 * 8; \
        unsigned _d = _db + _pl * 10240 + _row * 80 + tc16 * 16; \
        CP_ASYNC16(_d, _s); \
    } \
    CP_COMMIT(); \
} while (0)

__global__ void __launch_bounds__(256, 2) gemm_out(
    const u16* __restrict__ A16,
    const u16* __restrict__ Wh, const u16* __restrict__ Wl,
    const float* __restrict__ bias, float* __restrict__ Cf)
{
    extern __shared__ char gsm[];
    const unsigned sbase = smem_u32(gsm);
    const int tid  = threadIdx.x;
    const int lane = tid & 31;
    const int warp = tid >> 5;
    const int warp_m = warp & 1, warp_n = warp >> 1;
    const int bn = blockIdx.x, bm = blockIdx.y;

    const u16* srcs[3];
    srcs[0] = A16 + (size_t)(bm * 128) * DM;
    srcs[1] = Wh  + (size_t)(bn * 128) * DM;
    srcs[2] = Wl  + (size_t)(bn * 128) * DM;

    const int trow = tid >> 2;
    const int tc16 = tid & 3;

    float acc[4][4][4];
#pragma unroll
    for (int i = 0; i < 4; i++)
#pragma unroll
        for (int j = 0; j < 4; j++)
#pragma unroll
            for (int t = 0; t < 4; t++) acc[i][j][t] = 0.f;

    const unsigned OFF_A = 0, OFF_WH = 10240, OFF_WL = 20480;
    const unsigned a_row = warp_m*64 + (lane & 15);
    const unsigned a_kof = (lane >> 4) * 8;
    const unsigned b_row = warp_n*32 + (lane & 7) + ((lane & 16) >> 1);
    const unsigned b_kof = (lane & 8);

    GEMM_ISSUE(0, 0);

    const int NCHUNK = DM / 32;
    for (int c = 0; c < NCHUNK; c++) {
        CP_WAIT0();
        __syncthreads();
        if (c + 1 < NCHUNK) GEMM_ISSUE(c + 1, (c + 1) & 1);

        const unsigned st = sbase + (unsigned)(c & 1) * STAGE_B;
#pragma unroll
        for (int ks = 0; ks < 2; ks++) {
            const unsigned kbyte = (unsigned)(ks * 16) * 2;
            u32 bh[8], bl[8];
#pragma unroll
            for (int jp = 0; jp < 2; jp++) {
                unsigned roff = (b_row + jp*16) * (GP*2) + kbyte + b_kof*2;
                ldsm4(bh[jp*4+0], bh[jp*4+1], bh[jp*4+2], bh[jp*4+3],
                      st + OFF_WH + roff);
                ldsm4(bl[jp*4+0], bl[jp*4+1], bl[jp*4+2], bl[jp*4+3],
                      st + OFF_WL + roff);
            }
#pragma unroll
            for (int i = 0; i < 4; i++) {
                unsigned roff = (a_row + i*16) * (GP*2) + kbyte + a_kof*2;
                u32 ah[4];
                ldsm4(ah[0], ah[1], ah[2], ah[3], st + OFF_A + roff);
#pragma unroll
                for (int j = 0; j < 4; j++) {
                    mma16816h(acc[i][j], ah, &bh[j*2]);
                    mma16816h(acc[i][j], ah, &bl[j*2]);
                }
            }
        }
        __syncthreads();
    }

    const int gid = lane >> 2, tig = lane & 3;
#pragma unroll
    for (int i = 0; i < 4; i++) {
#pragma unroll
        for (int j = 0; j < 4; j++) {
            int gnc = bn*128 + warp_n*32 + j*8 + tig*2;
            float2 bv = *(const float2*)(bias + gnc);
#pragma unroll
            for (int half = 0; half < 2; half++) {
                int m = bm*128 + warp_m*64 + i*16 + gid + half*8;
                float o0 = acc[i][j][half*2+0] + bv.x;
                float o1 = acc[i][j][half*2+1] + bv.y;
                *(float2*)(Cf + (size_t)m * DM + gnc) = make_float2(o0, o1);
            }
        }
    }
}

// ---------------- attention: fp16 MMA, MUFU softmax (log2e pre-folded) ----
#define AQ 0
#define ABUF0 18432
#define ABUF1 36864
#define ASMEM_BYTES 55296

__global__ void __launch_bounds__(256, 2) attn_mma_kernel(
    const u16* __restrict__ Qh, const u16* __restrict__ Kh,
    const u16* __restrict__ Vh, u16* __restrict__ C16)
{
    extern __shared__ char asm_[];
    const unsigned sbase = smem_u32(asm_);
    const int tid  = threadIdx.x;
    const int lane = tid & 31;
    const int w    = tid >> 5;
    const int gid  = lane >> 2, tig = lane & 3;
    const int qt = blockIdx.x, h = blockIdx.y, b = blockIdx.z;
    const size_t bh = (size_t)(b*NH + h) * SEQ;

    const int unit = tid >> 1;
    const int uhalf = tid & 1;

    // KV tile 0
    {
        const u16* pl = (unit < 64) ? Kh : Vh;
        int row = unit & 63;
        const u16* src = pl + ((bh + row) << 6) + uhalf*32;
        unsigned dst = sbase + ABUF0 + ((unit < 64) ? 0u : 9216u)
                     + row*144 + uhalf*64;
#pragma unroll
        for (int i = 0; i < 4; i++) CP_ASYNC16(dst + i*16, src + i*8);
    }
    // Q tile
    {
        const u16* src = Qh + ((bh + qt*128 + unit) << 6) + uhalf*32;
        unsigned dst = sbase + AQ + unit*144 + uhalf*64;
#pragma unroll
        for (int i = 0; i < 4; i++) CP_ASYNC16(dst + i*16, src + i*8);
    }
    CP_COMMIT();
    CP_WAIT0();
    __syncthreads();

    u32 qf[4][4];
    {
        unsigned rbase = (unsigned)(w*16 + (lane & 15)) * 144 + (lane >> 4) * 16;
#pragma unroll
        for (int ks = 0; ks < 4; ks++)
            ldsm4(qf[ks][0], qf[ks][1], qf[ks][2], qf[ks][3],
                  sbase + AQ + rbase + ks*32);
    }

    float o_[8][4];
#pragma unroll
    for (int j = 0; j < 8; j++)
#pragma unroll
        for (int t = 0; t < 4; t++) o_[j][t] = 0.f;
    float l0 = 0.f, l1 = 0.f;

    const unsigned b_rowoff = ((lane & 7) + ((lane & 16) >> 1)) * 144 + (lane & 8) * 2;
    const unsigned v_rowoff = (lane & 15) * 144 + (lane >> 4) * 16;

    for (int kt = 0; kt < SEQ/64; kt++) {
        const unsigned cbuf = (kt & 1) ? ABUF1 : ABUF0;

        if (kt + 1 < SEQ/64) {
            const u16* pl = (unit < 64) ? Kh : Vh;
            int row = unit & 63;
            const u16* src = pl + ((bh + (kt+1)*64 + row) << 6) + uhalf*32;
            unsigned dst = sbase + ((kt & 1) ? ABUF0 : ABUF1)
                         + ((unit < 64) ? 0u : 9216u) + row*144 + uhalf*64;
#pragma unroll
            for (int i = 0; i < 4; i++) CP_ASYNC16(dst + i*16, src + i*8);
            CP_COMMIT();
        }

        // ---- QK^T (1 MMA per position) ----
        float s_[8][4];
#pragma unroll
        for (int j = 0; j < 8; j++)
#pragma unroll
            for (int t = 0; t < 4; t++) s_[j][t] = 0.f;

        u32 kf2[2][4];
        ldsm4(kf2[0][0], kf2[0][1], kf2[0][2], kf2[0][3],
              sbase + cbuf + b_rowoff);
#pragma unroll
        for (int it = 0; it < 16; it++) {
            const int ks = it >> 2, ng = it & 3;
            const int cur = it & 1;
            if (it + 1 < 16) {
                const int ks2 = (it + 1) >> 2, ng2 = (it + 1) & 3;
                unsigned roff = (unsigned)(ng2*16)*144 + b_rowoff + ks2*32;
                ldsm4(kf2[cur^1][0], kf2[cur^1][1], kf2[cur^1][2], kf2[cur^1][3],
                      sbase + cbuf + roff);
            }
            mma16816h(s_[2*ng+0], qf[ks], &kf2[cur][0]);
            mma16816h(s_[2*ng+1], qf[ks], &kf2[cur][2]);
        }

        // ---- p = 2^s (MUFU); P fp16; PV ----
        u32 vf2[2][4];
        ldsm4t(vf2[0][0], vf2[0][1], vf2[0][2], vf2[0][3],
               sbase + cbuf + 9216u + v_rowoff);
        u32 pa[4];
#pragma unroll
        for (int it = 0; it < 16; it++) {
            const int ks = it >> 2, ng = it & 3;
            const int cur = it & 1;
            if (it + 1 < 16) {
                const int ks2 = (it + 1) >> 2, ng2 = (it + 1) & 3;
                unsigned roff = (unsigned)(ks2*16)*144 + v_rowoff + (unsigned)(ng2*32);
                ldsm4t(vf2[cur^1][0], vf2[cur^1][1], vf2[cur^1][2], vf2[cur^1][3],
                       sbase + cbuf + 9216u + roff);
            }
            if (ng == 0) {
                float p0 = fex2(s_[2*ks+0][0]);
                float p1 = fex2(s_[2*ks+0][1]);
                float p2 = fex2(s_[2*ks+0][2]);
                float p3 = fex2(s_[2*ks+0][3]);
                float q0 = fex2(s_[2*ks+1][0]);
                float q1 = fex2(s_[2*ks+1][1]);
                float q2 = fex2(s_[2*ks+1][2]);
                float q3 = fex2(s_[2*ks+1][3]);
                l0 += (p0 + p1) + (q0 + q1);
                l1 += (p2 + p3) + (q2 + q3);
                pa[0] = packh2(p0, p1);
                pa[1] = packh2(p2, p3);
                pa[2] = packh2(q0, q1);
                pa[3] = packh2(q2, q3);
            }
            mma16816h(o_[2*ng+0], pa, &vf2[cur][0]);
            mma16816h(o_[2*ng+1], pa, &vf2[cur][2]);
        }

        CP_WAIT0();
        __syncthreads();
    }

    l0 += __shfl_xor_sync(0xffffffffu, l0, 1);
    l0 += __shfl_xor_sync(0xffffffffu, l0, 2);
    l1 += __shfl_xor_sync(0xffffffffu, l1, 1);
    l1 += __shfl_xor_sync(0xffffffffu, l1, 2);

    float inv0 = 1.f / l0, inv1 = 1.f / l1;
    int r0 = qt*128 + w*16 + gid;
    size_t base0 = ((size_t)(b*SEQ) + r0) * DM + h*64;
    size_t base1 = base0 + (size_t)8 * DM;
#pragma unroll
    for (int j = 0; j < 8; j++) {
        int d = j*8 + tig*2;
        *(u32*)(C16 + base0 + d) = packh2(o_[j][0]*inv0, o_[j][1]*inv0);
        *(u32*)(C16 + base1 + d) = packh2(o_[j][2]*inv1, o_[j][3]*inv1);
    }
}

// ---------------- launch ----------------
extern "C" void kernel_launch(void* const* d_in, const int* in_sizes, int n_in,
                              void* d_out, int out_size)
{
    const float* q    = (const float*)d_in[0];
    const float* k    = (const float*)d_in[1];
    const float* v    = (const float*)d_in[2];
    const float* wq_w = (const float*)d_in[3];
    const float* wq_b = (const float*)d_in[4];
    const float* wk_w = (const float*)d_in[5];
    const float* wk_b = (const float*)d_in[6];
    const float* wv_w = (const float*)d_in[7];
    const float* wv_b = (const float*)d_in[8];
    const float* wo_w = (const float*)d_in[9];
    const float* wo_b = (const float*)d_in[10];
    float* out = (float*)d_out;

    u16 *wh0, *wl0, *q16, *k16, *v16, *c16;
    cudaGetSymbolAddress((void**)&wh0, g_w_h);
    cudaGetSymbolAddress((void**)&wl0, g_w_l);
    cudaGetSymbolAddress((void**)&q16, g_q16);
    cudaGetSymbolAddress((void**)&k16, g_k16);
    cudaGetSymbolAddress((void**)&v16, g_v16);
    cudaGetSymbolAddress((void**)&c16, g_c16);
    const size_t WSZ = (size_t)DM * DM;

    cudaFuncSetAttribute(gemm_qkv,
                         cudaFuncAttributeMaxDynamicSharedMemorySize, GSMEM_BYTES);
    cudaFuncSetAttribute(gemm_out,
                         cudaFuncAttributeMaxDynamicSharedMemorySize, GSMEM_BYTES);
    cudaFuncSetAttribute(attn_mma_kernel,
                         cudaFuncAttributeMaxDynamicSharedMemorySize, ASMEM_BYTES);

    const int nW4 = DM*DM/4;
    const int cblk = 256;
    const int cgW = (nW4 + cblk - 1) / cblk;

    // weight conversions (wq,wk,wv at z slots 0..2; wo at slot 3)
    conv_w16<<<cgW, cblk>>>((const float4*)wq_w, (uint2*)(wh0 + 0*WSZ), (uint2*)(wl0 + 0*WSZ), nW4);
    conv_w16<<<cgW, cblk>>>((const float4*)wk_w, (uint2*)(wh0 + 1*WSZ), (uint2*)(wl0 + 1*WSZ), nW4);
    conv_w16<<<cgW, cblk>>>((const float4*)wv_w, (uint2*)(wh0 + 2*WSZ), (uint2*)(wl0 + 2*WSZ), nW4);
    conv_w16<<<cgW, cblk>>>((const float4*)wo_w, (uint2*)(wh0 + 3*WSZ), (uint2*)(wl0 + 3*WSZ), nW4);

    // fused Q/K/V projections (fp32 A converted in-loader; log2e folded into q)
    const float QSCALE = 0.125f * 1.4426950408889634f;
    dim3 gblk(256), qgrid(DM/128, MROWS/128, 3);   // (8, 64, 3)
    gemm_qkv<<<qgrid, gblk, GSMEM_BYTES>>>(q, k, v, wh0, wl0,
                                           wq_b, wk_b, wv_b,
                                           q16, k16, v16, QSCALE);

    // attention
    dim3 ablk(256), agrid(SEQ/128, NH, NB);
    attn_mma_kernel<<<agrid, ablk, ASMEM_BYTES>>>(q16, k16, v16, c16);

    // output projection
    dim3 ogrid(DM/128, MROWS/128);
    gemm_out<<<ogrid, gblk, GSMEM_BYTES>>>(c16, wh0 + 3*WSZ, wl0 + 3*WSZ,
                                           wo_b, out);
}

// round 14
// speedup vs baseline: 2.1280x; 1.0130x over previous
#include <cuda_runtime.h>
#include <cuda_fp16.h>
#include <cstdint>

#define NB   4
#define SEQ  2048
#define NH   16
#define DEP  64
#define DM   1024
#define MROWS (NB*SEQ)

typedef unsigned short u16;
typedef unsigned int   u32;

// ---------------- scratch ----------------
__device__ u16 g_w_h[4][(size_t)DM*DM];          // weights fp16 hi
__device__ u16 g_w_l[4][(size_t)DM*DM];          // weights fp16 residual
__device__ u16 g_q16[(size_t)MROWS*DM];          // fp16 head planes [B,H,S,64]
__device__ u16 g_k16[(size_t)MROWS*DM];
__device__ u16 g_v16[(size_t)MROWS*DM];
__device__ u16 g_c16[(size_t)MROWS*DM];          // ctx fp16 [B,S,DM]

// ---------------- helpers ----------------
__device__ __forceinline__ unsigned smem_u32(const void* p) {
    unsigned r;
    asm("{ .reg .u64 t; cvta.to.shared.u64 t, %1; cvt.u32.u64 %0, t; }"
        : "=r"(r) : "l"(p));
    return r;
}

__device__ __forceinline__ void ldsm4(u32& r0, u32& r1, u32& r2, u32& r3,
                                      unsigned addr) {
    asm volatile("ldmatrix.sync.aligned.m8n8.x4.shared.b16 {%0,%1,%2,%3}, [%4];"
                 : "=r"(r0), "=r"(r1), "=r"(r2), "=r"(r3) : "r"(addr));
}
__device__ __forceinline__ void ldsm4t(u32& r0, u32& r1, u32& r2, u32& r3,
                                       unsigned addr) {
    asm volatile("ldmatrix.sync.aligned.m8n8.x4.trans.shared.b16 {%0,%1,%2,%3}, [%4];"
                 : "=r"(r0), "=r"(r1), "=r"(r2), "=r"(r3) : "r"(addr));
}
// fp16 mma
__device__ __forceinline__ void mma16816h(float* d, const u32* a, const u32* b) {
    asm volatile("mma.sync.aligned.m16n8k16.row.col.f32.f16.f16.f32 "
                 "{%0,%1,%2,%3}, {%4,%5,%6,%7}, {%8,%9}, {%0,%1,%2,%3};"
                 : "+f"(d[0]), "+f"(d[1]), "+f"(d[2]), "+f"(d[3])
                 : "r"(a[0]), "r"(a[1]), "r"(a[2]), "r"(a[3]),
                   "r"(b[0]), "r"(b[1]));
}

#define CP_ASYNC16(dst, src) \
    asm volatile("cp.async.cg.shared.global [%0], [%1], 16;" :: "r"(dst), "l"(src))
#define CP_COMMIT() asm volatile("cp.async.commit_group;" ::: "memory")
#define CP_WAIT0()  asm volatile("cp.async.wait_group 0;" ::: "memory")

// 2^x via MUFU (exp folded: q pre-scaled by 0.125*log2e)
__device__ __forceinline__ float fex2(float x) {
    float r; asm("ex2.approx.f32 %0, %1;" : "=f"(r) : "f"(x)); return r;
}

// pack two fp32 -> fp16x2 (RN): lo = a, hi = b
__device__ __forceinline__ u32 packh2(float a, float b) {
    u32 d; asm("cvt.rn.f16x2.f32 %0, %1, %2;" : "=r"(d) : "f"(b), "f"(a));
    return d;
}
// fp16 (as low 16 bits) -> fp32
__device__ __forceinline__ float h2f(u32 hbits) {
    float f; asm("{ .reg .b16 t; mov.b16 t, %1; cvt.f32.f16 %0, t; }"
                 : "=f"(f) : "h"((unsigned short)hbits));
    return f;
}

// ---------------- weight conversion (all 4 weights in one launch) --------
__global__ void conv_w16(const float4* __restrict__ w0,
                         const float4* __restrict__ w1,
                         const float4* __restrict__ w2,
                         const float4* __restrict__ w3,
                         uint2* __restrict__ hi, uint2* __restrict__ lo, int n4)
{
    int i = blockIdx.x * blockDim.x + threadIdx.x;
    if (i >= n4) return;
    int z = blockIdx.y;
    const float4* src = (z == 0) ? w0 : (z == 1) ? w1 : (z == 2) ? w2 : w3;
    float4 v = src[i];
    u32 p01 = packh2(v.x, v.y);
    u32 p23 = packh2(v.z, v.w);
    float h0 = h2f(p01 & 0xffffu), h1 = h2f(p01 >> 16);
    float h2 = h2f(p23 & 0xffffu), h3 = h2f(p23 >> 16);
    size_t off = (size_t)z * (DM*DM/4) + i;
    hi[off] = make_uint2(p01, p23);
    lo[off] = make_uint2(packh2(v.x - h0, v.y - h1), packh2(v.z - h2, v.w - h3));
}

// ---------------- GEMM common geometry ----------------
#define GP 40
#define STAGE_B 30720
#define GSMEM_BYTES (2*STAGE_B)

// ---------------- fused QKV projection ----------------
__global__ void __launch_bounds__(256, 2) gemm_qkv(
    const float* __restrict__ Aq, const float* __restrict__ Ak,
    const float* __restrict__ Av,
    const u16* __restrict__ WhA, const u16* __restrict__ WlA,
    const float* __restrict__ bq, const float* __restrict__ bk,
    const float* __restrict__ bv,
    u16* __restrict__ Oq, u16* __restrict__ Ok, u16* __restrict__ Ov,
    float qscale)
{
    extern __shared__ char gsm[];
    const unsigned sbase = smem_u32(gsm);
    const int tid  = threadIdx.x;
    const int lane = tid & 31;
    const int warp = tid >> 5;
    const int warp_m = warp & 1, warp_n = warp >> 1;
    const int bn = blockIdx.x, bm = blockIdx.y, z = blockIdx.z;

    const float* A32 = ((z == 0) ? Aq : (z == 1) ? Ak : Av)
                     + (size_t)(bm * 128) * DM;
    const u16* Wh = WhA + (size_t)z * DM * DM + (size_t)(bn * 128) * DM;
    const u16* Wl = WlA + (size_t)z * DM * DM + (size_t)(bn * 128) * DM;
    const float* bias = (z == 0) ? bq : (z == 1) ? bk : bv;
    u16* C16 = (z == 0) ? Oq : (z == 1) ? Ok : Ov;
    const float scale = (z == 0) ? qscale : 1.0f;

    const int trow = tid >> 2;
    const int tc16 = tid & 3;
    const int arow = tid >> 3;
    const int af4  = tid & 7;

    float acc[4][4][4];
#pragma unroll
    for (int i = 0; i < 4; i++)
#pragma unroll
        for (int j = 0; j < 4; j++)
#pragma unroll
            for (int t = 0; t < 4; t++) acc[i][j][t] = 0.f;

    const unsigned OFF_A = 0, OFF_WH = 10240, OFF_WL = 20480;
    const unsigned a_row = warp_m*64 + (lane & 15);
    const unsigned a_kof = (lane >> 4) * 8;
    const unsigned b_row = warp_n*32 + (lane & 7) + ((lane & 16) >> 1);
    const unsigned b_kof = (lane & 8);

#define QKV_WISSUE(chunk, stage) do { \
    unsigned _db = sbase + (stage)*STAGE_B; \
    int _ck = (chunk) * 32; \
    _Pragma("unroll") \
    for (int _i = 0; _i < 4; _i++) { \
        int _pl = _i >> 1; \
        int _row = ((_i & 1) << 6) + trow; \
        const u16* _s = (_pl ? Wl : Wh) + (size_t)_row * DM + _ck + tc16 * 8; \
        unsigned _d = _db + OFF_WH + _pl * 10240 + _row * 80 + tc16 * 16; \
        CP_ASYNC16(_d, _s); \
    } \
    CP_COMMIT(); \
} while (0)

    float4 pa[4];
#define QKV_ALDG(chunk) do { \
    int _ck = (chunk) * 32; \
    _Pragma("unroll") \
    for (int _p = 0; _p < 4; _p++) { \
        int _row = _p*32 + arow; \
        pa[_p] = *(const float4*)(A32 + (size_t)_row * DM + _ck + af4*4); \
    } \
} while (0)

#define QKV_ASTS(stage) do { \
    char* _sp = gsm + (stage)*STAGE_B + OFF_A; \
    _Pragma("unroll") \
    for (int _p = 0; _p < 4; _p++) { \
        int _row = _p*32 + arow; \
        *(uint2*)(_sp + _row*80 + af4*8) = \
            make_uint2(packh2(pa[_p].x, pa[_p].y), packh2(pa[_p].z, pa[_p].w)); \
    } \
} while (0)

    QKV_WISSUE(0, 0);
    QKV_ALDG(0);

    const int NCHUNK = DM / 32;
    for (int c = 0; c < NCHUNK; c++) {
        const int st = c & 1;
        QKV_ASTS(st);
        CP_WAIT0();
        __syncthreads();
        if (c + 1 < NCHUNK) {
            QKV_WISSUE(c + 1, st ^ 1);
            QKV_ALDG(c + 1);
        }

        const unsigned sb = sbase + (unsigned)st * STAGE_B;
#pragma unroll
        for (int ks = 0; ks < 2; ks++) {
            const unsigned kbyte = (unsigned)(ks * 16) * 2;
            u32 bh[8], bl[8];
#pragma unroll
            for (int jp = 0; jp < 2; jp++) {
                unsigned roff = (b_row + jp*16) * (GP*2) + kbyte + b_kof*2;
                ldsm4(bh[jp*4+0], bh[jp*4+1], bh[jp*4+2], bh[jp*4+3],
                      sb + OFF_WH + roff);
                ldsm4(bl[jp*4+0], bl[jp*4+1], bl[jp*4+2], bl[jp*4+3],
                      sb + OFF_WL + roff);
            }
#pragma unroll
            for (int i = 0; i < 4; i++) {
                unsigned roff = (a_row + i*16) * (GP*2) + kbyte + a_kof*2;
                u32 ah[4];
                ldsm4(ah[0], ah[1], ah[2], ah[3], sb + OFF_A + roff);
#pragma unroll
                for (int j = 0; j < 4; j++) {
                    mma16816h(acc[i][j], ah, &bh[j*2]);
                    mma16816h(acc[i][j], ah, &bl[j*2]);
                }
            }
        }
        __syncthreads();
    }

    const int gid = lane >> 2, tig = lane & 3;
#pragma unroll
    for (int i = 0; i < 4; i++) {
#pragma unroll
        for (int j = 0; j < 4; j++) {
            int gnc = bn*128 + warp_n*32 + j*8 + tig*2;
            float2 bv = *(const float2*)(bias + gnc);
#pragma unroll
            for (int half = 0; half < 2; half++) {
                int m = bm*128 + warp_m*64 + i*16 + gid + half*8;
                float o0 = (acc[i][j][half*2+0] + bv.x) * scale;
                float o1 = (acc[i][j][half*2+1] + bv.y) * scale;
                int bi = m >> 11, s = m & (SEQ - 1);
                int hh = gnc >> 6, d = gnc & 63;
                size_t idx = (((size_t)(bi*NH + hh) * SEQ + s) << 6) + d;
                *(u32*)(C16 + idx) = packh2(o0, o1);
            }
        }
    }
}

// ---------------- output GEMM ----------------
#define GEMM_ISSUE(chunk, stage) do { \
    unsigned _db = sbase + (stage)*STAGE_B; \
    int _ck = (chunk) * 32; \
    _Pragma("unroll") \
    for (int _i = 0; _i < 6; _i++) { \
        int _pl = _i >> 1; \
        int _row = ((_i & 1) << 6) + trow; \
        const u16* _s = srcs[_pl] + (size_t)_row * DM + _ck + tc16 * 8; \
        unsigned _d = _db + _pl * 10240 + _row * 80 + tc16 * 16; \
        CP_ASYNC16(_d, _s); \
    } \
    CP_COMMIT(); \
} while (0)

__global__ void __launch_bounds__(256, 2) gemm_out(
    const u16* __restrict__ A16,
    const u16* __restrict__ Wh, const u16* __restrict__ Wl,
    const float* __restrict__ bias, float* __restrict__ Cf)
{
    extern __shared__ char gsm[];
    const unsigned sbase = smem_u32(gsm);
    const int tid  = threadIdx.x;
    const int lane = tid & 31;
    const int warp = tid >> 5;
    const int warp_m = warp & 1, warp_n = warp >> 1;
    const int bn = blockIdx.x, bm = blockIdx.y;

    const u16* srcs[3];
    srcs[0] = A16 + (size_t)(bm * 128) * DM;
    srcs[1] = Wh  + (size_t)(bn * 128) * DM;
    srcs[2] = Wl  + (size_t)(bn * 128) * DM;

    const int trow = tid >> 2;
    const int tc16 = tid & 3;

    float acc[4][4][4];
#pragma unroll
    for (int i = 0; i < 4; i++)
#pragma unroll
        for (int j = 0; j < 4; j++)
#pragma unroll
            for (int t = 0; t < 4; t++) acc[i][j][t] = 0.f;

    const unsigned OFF_A = 0, OFF_WH = 10240, OFF_WL = 20480;
    const unsigned a_row = warp_m*64 + (lane & 15);
    const unsigned a_kof = (lane >> 4) * 8;
    const unsigned b_row = warp_n*32 + (lane & 7) + ((lane & 16) >> 1);
    const unsigned b_kof = (lane & 8);

    GEMM_ISSUE(0, 0);

    const int NCHUNK = DM / 32;
    for (int c = 0; c < NCHUNK; c++) {
        CP_WAIT0();
        __syncthreads();
        if (c + 1 < NCHUNK) GEMM_ISSUE(c + 1, (c + 1) & 1);

        const unsigned st = sbase + (unsigned)(c & 1) * STAGE_B;
#pragma unroll
        for (int ks = 0; ks < 2; ks++) {
            const unsigned kbyte = (unsigned)(ks * 16) * 2;
            u32 bh[8], bl[8];
#pragma unroll
            for (int jp = 0; jp < 2; jp++) {
                unsigned roff = (b_row + jp*16) * (GP*2) + kbyte + b_kof*2;
                ldsm4(bh[jp*4+0], bh[jp*4+1], bh[jp*4+2], bh[jp*4+3],
                      st + OFF_WH + roff);
                ldsm4(bl[jp*4+0], bl[jp*4+1], bl[jp*4+2], bl[jp*4+3],
                      st + OFF_WL + roff);
            }
#pragma unroll
            for (int i = 0; i < 4; i++) {
                unsigned roff = (a_row + i*16) * (GP*2) + kbyte + a_kof*2;
                u32 ah[4];
                ldsm4(ah[0], ah[1], ah[2], ah[3], st + OFF_A + roff);
#pragma unroll
                for (int j = 0; j < 4; j++) {
                    mma16816h(acc[i][j], ah, &bh[j*2]);
                    mma16816h(acc[i][j], ah, &bl[j*2]);
                }
            }
        }
        __syncthreads();
    }

    const int gid = lane >> 2, tig = lane & 3;
#pragma unroll
    for (int i = 0; i < 4; i++) {
#pragma unroll
        for (int j = 0; j < 4; j++) {
            int gnc = bn*128 + warp_n*32 + j*8 + tig*2;
            float2 bv = *(const float2*)(bias + gnc);
#pragma unroll
            for (int half = 0; half < 2; half++) {
                int m = bm*128 + warp_m*64 + i*16 + gid + half*8;
                float o0 = acc[i][j][half*2+0] + bv.x;
                float o1 = acc[i][j][half*2+1] + bv.y;
                *(float2*)(Cf + (size_t)m * DM + gnc) = make_float2(o0, o1);
            }
        }
    }
}

// ---------------- attention: fused per-group QK->exp->PV ----------------
#define AQ 0
#define ABUF0 18432
#define ABUF1 36864
#define ASMEM_BYTES 55296

__global__ void __launch_bounds__(256, 2) attn_mma_kernel(
    const u16* __restrict__ Qh, const u16* __restrict__ Kh,
    const u16* __restrict__ Vh, u16* __restrict__ C16)
{
    extern __shared__ char asm_[];
    const unsigned sbase = smem_u32(asm_);
    const int tid  = threadIdx.x;
    const int lane = tid & 31;
    const int w    = tid >> 5;
    const int gid  = lane >> 2, tig = lane & 3;
    const int qt = blockIdx.x, h = blockIdx.y, b = blockIdx.z;
    const size_t bh = (size_t)(b*NH + h) * SEQ;

    const int unit = tid >> 1;
    const int uhalf = tid & 1;

    // KV tile 0
    {
        const u16* pl = (unit < 64) ? Kh : Vh;
        int row = unit & 63;
        const u16* src = pl + ((bh + row) << 6) + uhalf*32;
        unsigned dst = sbase + ABUF0 + ((unit < 64) ? 0u : 9216u)
                     + row*144 + uhalf*64;
#pragma unroll
        for (int i = 0; i < 4; i++) CP_ASYNC16(dst + i*16, src + i*8);
    }
    // Q tile
    {
        const u16* src = Qh + ((bh + qt*128 + unit) << 6) + uhalf*32;
        unsigned dst = sbase + AQ + unit*144 + uhalf*64;
#pragma unroll
        for (int i = 0; i < 4; i++) CP_ASYNC16(dst + i*16, src + i*8);
    }
    CP_COMMIT();
    CP_WAIT0();
    __syncthreads();

    u32 qf[4][4];
    {
        unsigned rbase = (unsigned)(w*16 + (lane & 15)) * 144 + (lane >> 4) * 16;
#pragma unroll
        for (int ks = 0; ks < 4; ks++)
            ldsm4(qf[ks][0], qf[ks][1], qf[ks][2], qf[ks][3],
                  sbase + AQ + rbase + ks*32);
    }

    float o_[8][4];
#pragma unroll
    for (int j = 0; j < 8; j++)
#pragma unroll
        for (int t = 0; t < 4; t++) o_[j][t] = 0.f;
    float l0 = 0.f, l1 = 0.f;

    const unsigned b_rowoff = ((lane & 7) + ((lane & 16) >> 1)) * 144 + (lane & 8) * 2;
    const unsigned v_rowoff = (lane & 15) * 144 + (lane >> 4) * 16;

    for (int kt = 0; kt < SEQ/64; kt++) {
        const unsigned cbuf = (kt & 1) ? ABUF1 : ABUF0;

        if (kt + 1 < SEQ/64) {
            const u16* pl = (unit < 64) ? Kh : Vh;
            int row = unit & 63;
            const u16* src = pl + ((bh + (kt+1)*64 + row) << 6) + uhalf*32;
            unsigned dst = sbase + ((kt & 1) ? ABUF0 : ABUF1)
                         + ((unit < 64) ? 0u : 9216u) + row*144 + uhalf*64;
#pragma unroll
            for (int i = 0; i < 4; i++) CP_ASYNC16(dst + i*16, src + i*8);
            CP_COMMIT();
        }

        // preload K frags for group 0
        u32 kf[4][4];
#pragma unroll
        for (int ks = 0; ks < 4; ks++)
            ldsm4(kf[ks][0], kf[ks][1], kf[ks][2], kf[ks][3],
                  sbase + cbuf + b_rowoff + ks*32);

        // ---- fused per score-group pipeline ----
#pragma unroll
        for (int g = 0; g < 4; g++) {
            // V frags for this kv group (issued early; latency hides under QK)
            u32 vf[4][4];
            unsigned vbase = (unsigned)(g*16)*144 + v_rowoff;
#pragma unroll
            for (int ngv = 0; ngv < 4; ngv++)
                ldsm4t(vf[ngv][0], vf[ngv][1], vf[ngv][2], vf[ngv][3],
                       sbase + cbuf + 9216u + vbase + ngv*32);

            // QK MMAs for group g (K frags preloaded)
            float s0[4] = {0.f, 0.f, 0.f, 0.f};
            float s1[4] = {0.f, 0.f, 0.f, 0.f};
#pragma unroll
            for (int ks = 0; ks < 4; ks++) {
                mma16816h(s0, qf[ks], &kf[ks][0]);
                mma16816h(s1, qf[ks], &kf[ks][2]);
            }

            // prefetch K frags for group g+1
            if (g < 3) {
                unsigned roff = (unsigned)((g+1)*16)*144 + b_rowoff;
#pragma unroll
                for (int ks = 0; ks < 4; ks++)
                    ldsm4(kf[ks][0], kf[ks][1], kf[ks][2], kf[ks][3],
                          sbase + cbuf + roff + ks*32);
            }

            // exp + pack (MUFU/FMA overlap with next group's ldsm/MMA)
            float p0 = fex2(s0[0]), p1 = fex2(s0[1]);
            float p2 = fex2(s0[2]), p3 = fex2(s0[3]);
            float q0 = fex2(s1[0]), q1 = fex2(s1[1]);
            float q2 = fex2(s1[2]), q3 = fex2(s1[3]);
            l0 += (p0 + p1) + (q0 + q1);
            l1 += (p2 + p3) + (q2 + q3);
            u32 pa[4];
            pa[0] = packh2(p0, p1);
            pa[1] = packh2(p2, p3);
            pa[2] = packh2(q0, q1);
            pa[3] = packh2(q2, q3);

            // PV MMAs for group g
#pragma unroll
            for (int ngv = 0; ngv < 4; ngv++) {
                mma16816h(o_[2*ngv+0], pa, &vf[ngv][0]);
                mma16816h(o_[2*ngv+1], pa, &vf[ngv][2]);
            }
        }

        CP_WAIT0();
        __syncthreads();
    }

    l0 += __shfl_xor_sync(0xffffffffu, l0, 1);
    l0 += __shfl_xor_sync(0xffffffffu, l0, 2);
    l1 += __shfl_xor_sync(0xffffffffu, l1, 1);
    l1 += __shfl_xor_sync(0xffffffffu, l1, 2);

    float inv0 = 1.f / l0, inv1 = 1.f / l1;
    int r0 = qt*128 + w*16 + gid;
    size_t base0 = ((size_t)(b*SEQ) + r0) * DM + h*64;
    size_t base1 = base0 + (size_t)8 * DM;
#pragma unroll
    for (int j = 0; j < 8; j++) {
        int d = j*8 + tig*2;
        *(u32*)(C16 + base0 + d) = packh2(o_[j][0]*inv0, o_[j][1]*inv0);
        *(u32*)(C16 + base1 + d) = packh2(o_[j][2]*inv1, o_[j][3]*inv1);
    }
}

// ---------------- launch ----------------
extern "C" void kernel_launch(void* const* d_in, const int* in_sizes, int n_in,
                              void* d_out, int out_size)
{
    const float* q    = (const float*)d_in[0];
    const float* k    = (const float*)d_in[1];
    const float* v    = (const float*)d_in[2];
    const float* wq_w = (const float*)d_in[3];
    const float* wq_b = (const float*)d_in[4];
    const float* wk_w = (const float*)d_in[5];
    const float* wk_b = (const float*)d_in[6];
    const float* wv_w = (const float*)d_in[7];
    const float* wv_b = (const float*)d_in[8];
    const float* wo_w = (const float*)d_in[9];
    const float* wo_b = (const float*)d_in[10];
    float* out = (float*)d_out;

    u16 *wh0, *wl0, *q16, *k16, *v16, *c16;
    cudaGetSymbolAddress((void**)&wh0, g_w_h);
    cudaGetSymbolAddress((void**)&wl0, g_w_l);
    cudaGetSymbolAddress((void**)&q16, g_q16);
    cudaGetSymbolAddress((void**)&k16, g_k16);
    cudaGetSymbolAddress((void**)&v16, g_v16);
    cudaGetSymbolAddress((void**)&c16, g_c16);
    const size_t WSZ = (size_t)DM * DM;

    cudaFuncSetAttribute(gemm_qkv,
                         cudaFuncAttributeMaxDynamicSharedMemorySize, GSMEM_BYTES);
    cudaFuncSetAttribute(gemm_out,
                         cudaFuncAttributeMaxDynamicSharedMemorySize, GSMEM_BYTES);
    cudaFuncSetAttribute(attn_mma_kernel,
                         cudaFuncAttributeMaxDynamicSharedMemorySize, ASMEM_BYTES);

    const int nW4 = DM*DM/4;
    const int cblk = 256;
    const int cgW = (nW4 + cblk - 1) / cblk;

    // all 4 weight conversions in one launch
    dim3 wgrid(cgW, 4);
    conv_w16<<<wgrid, cblk>>>((const float4*)wq_w, (const float4*)wk_w,
                              (const float4*)wv_w, (const float4*)wo_w,
                              (uint2*)wh0, (uint2*)wl0, nW4);

    // fused Q/K/V projections
    const float QSCALE = 0.125f * 1.4426950408889634f;
    dim3 gblk(256), qgrid(DM/128, MROWS/128, 3);
    gemm_qkv<<<qgrid, gblk, GSMEM_BYTES>>>(q, k, v, wh0, wl0,
                                           wq_b, wk_b, wv_b,
                                           q16, k16, v16, QSCALE);

    // attention
    dim3 ablk(256), agrid(SEQ/128, NH, NB);
    attn_mma_kernel<<<agrid, ablk, ASMEM_BYTES>>>(q16, k16, v16, c16);

    // output projection
    dim3 ogrid(DM/128, MROWS/128);
    gemm_out<<<ogrid, gblk, GSMEM_BYTES>>>(c16, wh0 + 3*WSZ, wl0 + 3*WSZ,
                                           wo_b, out);
}

// round 15
// speedup vs baseline: 2.8051x; 1.3182x over previous
#include <cuda_runtime.h>
#include <cuda_fp16.h>
#include <cstdint>

#define NB   4
#define SEQ  2048
#define NH   16
#define DEP  64
#define DM   1024
#define MROWS (NB*SEQ)

typedef unsigned short u16;
typedef unsigned int   u32;

// ---------------- scratch ----------------
__device__ u16 g_w16[4][(size_t)DM*DM];          // weights fp16 (single plane)
__device__ u16 g_q16[(size_t)MROWS*DM];          // fp16 head planes [B,H,S,64]
__device__ u16 g_k16[(size_t)MROWS*DM];
__device__ u16 g_v16[(size_t)MROWS*DM];
__device__ u16 g_c16[(size_t)MROWS*DM];          // ctx fp16 [B,S,DM]

// ---------------- helpers ----------------
__device__ __forceinline__ unsigned smem_u32(const void* p) {
    unsigned r;
    asm("{ .reg .u64 t; cvta.to.shared.u64 t, %1; cvt.u32.u64 %0, t; }"
        : "=r"(r) : "l"(p));
    return r;
}

__device__ __forceinline__ void ldsm4(u32& r0, u32& r1, u32& r2, u32& r3,
                                      unsigned addr) {
    asm volatile("ldmatrix.sync.aligned.m8n8.x4.shared.b16 {%0,%1,%2,%3}, [%4];"
                 : "=r"(r0), "=r"(r1), "=r"(r2), "=r"(r3) : "r"(addr));
}
__device__ __forceinline__ void ldsm4t(u32& r0, u32& r1, u32& r2, u32& r3,
                                       unsigned addr) {
    asm volatile("ldmatrix.sync.aligned.m8n8.x4.trans.shared.b16 {%0,%1,%2,%3}, [%4];"
                 : "=r"(r0), "=r"(r1), "=r"(r2), "=r"(r3) : "r"(addr));
}
// fp16 mma
__device__ __forceinline__ void mma16816h(float* d, const u32* a, const u32* b) {
    asm volatile("mma.sync.aligned.m16n8k16.row.col.f32.f16.f16.f32 "
                 "{%0,%1,%2,%3}, {%4,%5,%6,%7}, {%8,%9}, {%0,%1,%2,%3};"
                 : "+f"(d[0]), "+f"(d[1]), "+f"(d[2]), "+f"(d[3])
                 : "r"(a[0]), "r"(a[1]), "r"(a[2]), "r"(a[3]),
                   "r"(b[0]), "r"(b[1]));
}

#define CP_ASYNC16(dst, src) \
    asm volatile("cp.async.cg.shared.global [%0], [%1], 16;" :: "r"(dst), "l"(src))
#define CP_COMMIT() asm volatile("cp.async.commit_group;" ::: "memory")
#define CP_WAIT0()  asm volatile("cp.async.wait_group 0;" ::: "memory")

// 2^x via MUFU (exp folded: q pre-scaled by 0.125*log2e)
__device__ __forceinline__ float fex2(float x) {
    float r; asm("ex2.approx.f32 %0, %1;" : "=f"(r) : "f"(x)); return r;
}

// pack two fp32 -> fp16x2 (RN): lo = a, hi = b
__device__ __forceinline__ u32 packh2(float a, float b) {
    u32 d; asm("cvt.rn.f16x2.f32 %0, %1, %2;" : "=r"(d) : "f"(b), "f"(a));
    return d;
}

// ---------------- weight conversion (all 4 weights, single fp16 plane) ----
__global__ void conv_w16(const float4* __restrict__ w0,
                         const float4* __restrict__ w1,
                         const float4* __restrict__ w2,
                         const float4* __restrict__ w3,
                         uint2* __restrict__ out, int n4)
{
    int i = blockIdx.x * blockDim.x + threadIdx.x;
    if (i >= n4) return;
    int z = blockIdx.y;
    const float4* src = (z == 0) ? w0 : (z == 1) ? w1 : (z == 2) ? w2 : w3;
    float4 v = src[i];
    out[(size_t)z * (DM*DM/4) + i] =
        make_uint2(packh2(v.x, v.y), packh2(v.z, v.w));
}

// ---------------- GEMM common geometry ----------------
// 128x128 tile, BK=32, 8 warps (2x4). Stage: A fp16 [128][40] + W fp16 [128][40].
#define GP 40
#define STAGE_B 20480
#define GSMEM_BYTES (2*STAGE_B)

// ---------------- fused QKV projection: fp32 A in, fp16 head planes out ---
__global__ void __launch_bounds__(256, 2) gemm_qkv(
    const float* __restrict__ Aq, const float* __restrict__ Ak,
    const float* __restrict__ Av,
    const u16* __restrict__ WA,
    const float* __restrict__ bq, const float* __restrict__ bk,
    const float* __restrict__ bv,
    u16* __restrict__ Oq, u16* __restrict__ Ok, u16* __restrict__ Ov,
    float qscale)
{
    extern __shared__ char gsm[];
    const unsigned sbase = smem_u32(gsm);
    const int tid  = threadIdx.x;
    const int lane = tid & 31;
    const int warp = tid >> 5;
    const int warp_m = warp & 1, warp_n = warp >> 1;
    const int bn = blockIdx.x, bm = blockIdx.y, z = blockIdx.z;

    const float* A32 = ((z == 0) ? Aq : (z == 1) ? Ak : Av)
                     + (size_t)(bm * 128) * DM;
    const u16* W = WA + (size_t)z * DM * DM + (size_t)(bn * 128) * DM;
    const float* bias = (z == 0) ? bq : (z == 1) ? bk : bv;
    u16* C16 = (z == 0) ? Oq : (z == 1) ? Ok : Ov;
    const float scale = (z == 0) ? qscale : 1.0f;

    const int trow = tid >> 2;          // 0..63 (W loader)
    const int tc16 = tid & 3;
    const int arow = tid >> 3;          // 0..31 (A loader)
    const int af4  = tid & 7;

    float acc[4][4][4];
#pragma unroll
    for (int i = 0; i < 4; i++)
#pragma unroll
        for (int j = 0; j < 4; j++)
#pragma unroll
            for (int t = 0; t < 4; t++) acc[i][j][t] = 0.f;

    const unsigned OFF_A = 0, OFF_W = 10240;
    const unsigned a_row = warp_m*64 + (lane & 15);
    const unsigned a_kof = (lane >> 4) * 8;
    const unsigned b_row = warp_n*32 + (lane & 7) + ((lane & 16) >> 1);
    const unsigned b_kof = (lane & 8);

#define QKV_WISSUE(chunk, stage) do { \
    unsigned _db = sbase + (stage)*STAGE_B; \
    int _ck = (chunk) * 32; \
    _Pragma("unroll") \
    for (int _i = 0; _i < 2; _i++) { \
        int _row = (_i << 6) + trow; \
        const u16* _s = W + (size_t)_row * DM + _ck + tc16 * 8; \
        unsigned _d = _db + OFF_W + _row * 80 + tc16 * 16; \
        CP_ASYNC16(_d, _s); \
    } \
    CP_COMMIT(); \
} while (0)

    float4 pa[4];
#define QKV_ALDG(chunk) do { \
    int _ck = (chunk) * 32; \
    _Pragma("unroll") \
    for (int _p = 0; _p < 4; _p++) { \
        int _row = _p*32 + arow; \
        pa[_p] = *(const float4*)(A32 + (size_t)_row * DM + _ck + af4*4); \
    } \
} while (0)

#define QKV_ASTS(stage) do { \
    char* _sp = gsm + (stage)*STAGE_B + OFF_A; \
    _Pragma("unroll") \
    for (int _p = 0; _p < 4; _p++) { \
        int _row = _p*32 + arow; \
        *(uint2*)(_sp + _row*80 + af4*8) = \
            make_uint2(packh2(pa[_p].x, pa[_p].y), packh2(pa[_p].z, pa[_p].w)); \
    } \
} while (0)

    QKV_WISSUE(0, 0);
    QKV_ALDG(0);

    const int NCHUNK = DM / 32;
    for (int c = 0; c < NCHUNK; c++) {
        const int st = c & 1;
        QKV_ASTS(st);
        CP_WAIT0();
        __syncthreads();
        if (c + 1 < NCHUNK) {
            QKV_WISSUE(c + 1, st ^ 1);
            QKV_ALDG(c + 1);
        }

        const unsigned sb = sbase + (unsigned)st * STAGE_B;
#pragma unroll
        for (int ks = 0; ks < 2; ks++) {
            const unsigned kbyte = (unsigned)(ks * 16) * 2;
            u32 bh[8];
#pragma unroll
            for (int jp = 0; jp < 2; jp++) {
                unsigned roff = (b_row + jp*16) * (GP*2) + kbyte + b_kof*2;
                ldsm4(bh[jp*4+0], bh[jp*4+1], bh[jp*4+2], bh[jp*4+3],
                      sb + OFF_W + roff);
            }
#pragma unroll
            for (int i = 0; i < 4; i++) {
                unsigned roff = (a_row + i*16) * (GP*2) + kbyte + a_kof*2;
                u32 ah[4];
                ldsm4(ah[0], ah[1], ah[2], ah[3], sb + OFF_A + roff);
#pragma unroll
                for (int j = 0; j < 4; j++)
                    mma16816h(acc[i][j], ah, &bh[j*2]);
            }
        }
        __syncthreads();
    }

    // epilogue: fp16 head plane [B,H,S,64]
    const int gid = lane >> 2, tig = lane & 3;
#pragma unroll
    for (int i = 0; i < 4; i++) {
#pragma unroll
        for (int j = 0; j < 4; j++) {
            int gnc = bn*128 + warp_n*32 + j*8 + tig*2;
            float2 bv = *(const float2*)(bias + gnc);
#pragma unroll
            for (int half = 0; half < 2; half++) {
                int m = bm*128 + warp_m*64 + i*16 + gid + half*8;
                float o0 = (acc[i][j][half*2+0] + bv.x) * scale;
                float o1 = (acc[i][j][half*2+1] + bv.y) * scale;
                int bi = m >> 11, s = m & (SEQ - 1);
                int hh = gnc >> 6, d = gnc & 63;
                size_t idx = (((size_t)(bi*NH + hh) * SEQ + s) << 6) + d;
                *(u32*)(C16 + idx) = packh2(o0, o1);
            }
        }
    }
}

// ---------------- output GEMM: fp16 A via cp.async, fp32 out -------------
#define GEMM_ISSUE(chunk, stage) do { \
    unsigned _db = sbase + (stage)*STAGE_B; \
    int _ck = (chunk) * 32; \
    _Pragma("unroll") \
    for (int _i = 0; _i < 4; _i++) { \
        int _pl = _i >> 1; \
        int _row = ((_i & 1) << 6) + trow; \
        const u16* _s = srcs[_pl] + (size_t)_row * DM + _ck + tc16 * 8; \
        unsigned _d = _db + _pl * 10240 + _row * 80 + tc16 * 16; \
        CP_ASYNC16(_d, _s); \
    } \
    CP_COMMIT(); \
} while (0)

__global__ void __launch_bounds__(256, 2) gemm_out(
    const u16* __restrict__ A16, const u16* __restrict__ W,
    const float* __restrict__ bias, float* __restrict__ Cf)
{
    extern __shared__ char gsm[];
    const unsigned sbase = smem_u32(gsm);
    const int tid  = threadIdx.x;
    const int lane = tid & 31;
    const int warp = tid >> 5;
    const int warp_m = warp & 1, warp_n = warp >> 1;
    const int bn = blockIdx.x, bm = blockIdx.y;

    const u16* srcs[2];
    srcs[0] = A16 + (size_t)(bm * 128) * DM;
    srcs[1] = W   + (size_t)(bn * 128) * DM;

    const int trow = tid >> 2;
    const int tc16 = tid & 3;

    float acc[4][4][4];
#pragma unroll
    for (int i = 0; i < 4; i++)
#pragma unroll
        for (int j = 0; j < 4; j++)
#pragma unroll
            for (int t = 0; t < 4; t++) acc[i][j][t] = 0.f;

    const unsigned OFF_A = 0, OFF_W = 10240;
    const unsigned a_row = warp_m*64 + (lane & 15);
    const unsigned a_kof = (lane >> 4) * 8;
    const unsigned b_row = warp_n*32 + (lane & 7) + ((lane & 16) >> 1);
    const unsigned b_kof = (lane & 8);

    GEMM_ISSUE(0, 0);

    const int NCHUNK = DM / 32;
    for (int c = 0; c < NCHUNK; c++) {
        CP_WAIT0();
        __syncthreads();
        if (c + 1 < NCHUNK) GEMM_ISSUE(c + 1, (c + 1) & 1);

        const unsigned st = sbase + (unsigned)(c & 1) * STAGE_B;
#pragma unroll
        for (int ks = 0; ks < 2; ks++) {
            const unsigned kbyte = (unsigned)(ks * 16) * 2;
            u32 bh[8];
#pragma unroll
            for (int jp = 0; jp < 2; jp++) {
                unsigned roff = (b_row + jp*16) * (GP*2) + kbyte + b_kof*2;
                ldsm4(bh[jp*4+0], bh[jp*4+1], bh[jp*4+2], bh[jp*4+3],
                      st + OFF_W + roff);
            }
#pragma unroll
            for (int i = 0; i < 4; i++) {
                unsigned roff = (a_row + i*16) * (GP*2) + kbyte + a_kof*2;
                u32 ah[4];
                ldsm4(ah[0], ah[1], ah[2], ah[3], st + OFF_A + roff);
#pragma unroll
                for (int j = 0; j < 4; j++)
                    mma16816h(acc[i][j], ah, &bh[j*2]);
            }
        }
        __syncthreads();
    }

    const int gid = lane >> 2, tig = lane & 3;
#pragma unroll
    for (int i = 0; i < 4; i++) {
#pragma unroll
        for (int j = 0; j < 4; j++) {
            int gnc = bn*128 + warp_n*32 + j*8 + tig*2;
            float2 bv = *(const float2*)(bias + gnc);
#pragma unroll
            for (int half = 0; half < 2; half++) {
                int m = bm*128 + warp_m*64 + i*16 + gid + half*8;
                float o0 = acc[i][j][half*2+0] + bv.x;
                float o1 = acc[i][j][half*2+1] + bv.y;
                *(float2*)(Cf + (size_t)m * DM + gnc) = make_float2(o0, o1);
            }
        }
    }
}

// ---------------- attention: fused per-group QK->exp->PV (round-14) ------
#define AQ 0
#define ABUF0 18432
#define ABUF1 36864
#define ASMEM_BYTES 55296

__global__ void __launch_bounds__(256, 2) attn_mma_kernel(
    const u16* __restrict__ Qh, const u16* __restrict__ Kh,
    const u16* __restrict__ Vh, u16* __restrict__ C16)
{
    extern __shared__ char asm_[];
    const unsigned sbase = smem_u32(asm_);
    const int tid  = threadIdx.x;
    const int lane = tid & 31;
    const int w    = tid >> 5;
    const int gid  = lane >> 2, tig = lane & 3;
    const int qt = blockIdx.x, h = blockIdx.y, b = blockIdx.z;
    const size_t bh = (size_t)(b*NH + h) * SEQ;

    const int unit = tid >> 1;
    const int uhalf = tid & 1;

    // KV tile 0
    {
        const u16* pl = (unit < 64) ? Kh : Vh;
        int row = unit & 63;
        const u16* src = pl + ((bh + row) << 6) + uhalf*32;
        unsigned dst = sbase + ABUF0 + ((unit < 64) ? 0u : 9216u)
                     + row*144 + uhalf*64;
#pragma unroll
        for (int i = 0; i < 4; i++) CP_ASYNC16(dst + i*16, src + i*8);
    }
    // Q tile
    {
        const u16* src = Qh + ((bh + qt*128 + unit) << 6) + uhalf*32;
        unsigned dst = sbase + AQ + unit*144 + uhalf*64;
#pragma unroll
        for (int i = 0; i < 4; i++) CP_ASYNC16(dst + i*16, src + i*8);
    }
    CP_COMMIT();
    CP_WAIT0();
    __syncthreads();

    u32 qf[4][4];
    {
        unsigned rbase = (unsigned)(w*16 + (lane & 15)) * 144 + (lane >> 4) * 16;
#pragma unroll
        for (int ks = 0; ks < 4; ks++)
            ldsm4(qf[ks][0], qf[ks][1], qf[ks][2], qf[ks][3],
                  sbase + AQ + rbase + ks*32);
    }

    float o_[8][4];
#pragma unroll
    for (int j = 0; j < 8; j++)
#pragma unroll
        for (int t = 0; t < 4; t++) o_[j][t] = 0.f;
    float l0 = 0.f, l1 = 0.f;

    const unsigned b_rowoff = ((lane & 7) + ((lane & 16) >> 1)) * 144 + (lane & 8) * 2;
    const unsigned v_rowoff = (lane & 15) * 144 + (lane >> 4) * 16;

    for (int kt = 0; kt < SEQ/64; kt++) {
        const unsigned cbuf = (kt & 1) ? ABUF1 : ABUF0;

        if (kt + 1 < SEQ/64) {
            const u16* pl = (unit < 64) ? Kh : Vh;
            int row = unit & 63;
            const u16* src = pl + ((bh + (kt+1)*64 + row) << 6) + uhalf*32;
            unsigned dst = sbase + ((kt & 1) ? ABUF0 : ABUF1)
                         + ((unit < 64) ? 0u : 9216u) + row*144 + uhalf*64;
#pragma unroll
            for (int i = 0; i < 4; i++) CP_ASYNC16(dst + i*16, src + i*8);
            CP_COMMIT();
        }

        u32 kf[4][4];
#pragma unroll
        for (int ks = 0; ks < 4; ks++)
            ldsm4(kf[ks][0], kf[ks][1], kf[ks][2], kf[ks][3],
                  sbase + cbuf + b_rowoff + ks*32);

#pragma unroll
        for (int g = 0; g < 4; g++) {
            u32 vf[4][4];
            unsigned vbase = (unsigned)(g*16)*144 + v_rowoff;
#pragma unroll
            for (int ngv = 0; ngv < 4; ngv++)
                ldsm4t(vf[ngv][0], vf[ngv][1], vf[ngv][2], vf[ngv][3],
                       sbase + cbuf + 9216u + vbase + ngv*32);

            float s0[4] = {0.f, 0.f, 0.f, 0.f};
            float s1[4] = {0.f, 0.f, 0.f, 0.f};
#pragma unroll
            for (int ks = 0; ks < 4; ks++) {
                mma16816h(s0, qf[ks], &kf[ks][0]);
                mma16816h(s1, qf[ks], &kf[ks][2]);
            }

            if (g < 3) {
                unsigned roff = (unsigned)((g+1)*16)*144 + b_rowoff;
#pragma unroll
                for (int ks = 0; ks < 4; ks++)
                    ldsm4(kf[ks][0], kf[ks][1], kf[ks][2], kf[ks][3],
                          sbase + cbuf + roff + ks*32);
            }

            float p0 = fex2(s0[0]), p1 = fex2(s0[1]);
            float p2 = fex2(s0[2]), p3 = fex2(s0[3]);
            float q0 = fex2(s1[0]), q1 = fex2(s1[1]);
            float q2 = fex2(s1[2]), q3 = fex2(s1[3]);
            l0 += (p0 + p1) + (q0 + q1);
            l1 += (p2 + p3) + (q2 + q3);
            u32 pa[4];
            pa[0] = packh2(p0, p1);
            pa[1] = packh2(p2, p3);
            pa[2] = packh2(q0, q1);
            pa[3] = packh2(q2, q3);

#pragma unroll
            for (int ngv = 0; ngv < 4; ngv++) {
                mma16816h(o_[2*ngv+0], pa, &vf[ngv][0]);
                mma16816h(o_[2*ngv+1], pa, &vf[ngv][2]);
            }
        }

        CP_WAIT0();
        __syncthreads();
    }

    l0 += __shfl_xor_sync(0xffffffffu, l0, 1);
    l0 += __shfl_xor_sync(0xffffffffu, l0, 2);
    l1 += __shfl_xor_sync(0xffffffffu, l1, 1);
    l1 += __shfl_xor_sync(0xffffffffu, l1, 2);

    float inv0 = 1.f / l0, inv1 = 1.f / l1;
    int r0 = qt*128 + w*16 + gid;
    size_t base0 = ((size_t)(b*SEQ) + r0) * DM + h*64;
    size_t base1 = base0 + (size_t)8 * DM;
#pragma unroll
    for (int j = 0; j < 8; j++) {
        int d = j*8 + tig*2;
        *(u32*)(C16 + base0 + d) = packh2(o_[j][0]*inv0, o_[j][1]*inv0);
        *(u32*)(C16 + base1 + d) = packh2(o_[j][2]*inv1, o_[j][3]*inv1);
    }
}

// ---------------- launch ----------------
extern "C" void kernel_launch(void* const* d_in, const int* in_sizes, int n_in,
                              void* d_out, int out_size)
{
    const float* q    = (const float*)d_in[0];
    const float* k    = (const float*)d_in[1];
    const float* v    = (const float*)d_in[2];
    const float* wq_w = (const float*)d_in[3];
    const float* wq_b = (const float*)d_in[4];
    const float* wk_w = (const float*)d_in[5];
    const float* wk_b = (const float*)d_in[6];
    const float* wv_w = (const float*)d_in[7];
    const float* wv_b = (const float*)d_in[8];
    const float* wo_w = (const float*)d_in[9];
    const float* wo_b = (const float*)d_in[10];
    float* out = (float*)d_out;

    u16 *w16, *q16, *k16, *v16, *c16;
    cudaGetSymbolAddress((void**)&w16, g_w16);
    cudaGetSymbolAddress((void**)&q16, g_q16);
    cudaGetSymbolAddress((void**)&k16, g_k16);
    cudaGetSymbolAddress((void**)&v16, g_v16);
    cudaGetSymbolAddress((void**)&c16, g_c16);
    const size_t WSZ = (size_t)DM * DM;

    cudaFuncSetAttribute(gemm_qkv,
                         cudaFuncAttributeMaxDynamicSharedMemorySize, GSMEM_BYTES);
    cudaFuncSetAttribute(gemm_out,
                         cudaFuncAttributeMaxDynamicSharedMemorySize, GSMEM_BYTES);
    cudaFuncSetAttribute(attn_mma_kernel,
                         cudaFuncAttributeMaxDynamicSharedMemorySize, ASMEM_BYTES);

    const int nW4 = DM*DM/4;
    const int cblk = 256;
    const int cgW = (nW4 + cblk - 1) / cblk;

    dim3 wgrid(cgW, 4);
    conv_w16<<<wgrid, cblk>>>((const float4*)wq_w, (const float4*)wk_w,
                              (const float4*)wv_w, (const float4*)wo_w,
                              (uint2*)w16, nW4);

    const float QSCALE = 0.125f * 1.4426950408889634f;
    dim3 gblk(256), qgrid(DM/128, MROWS/128, 3);
    gemm_qkv<<<qgrid, gblk, GSMEM_BYTES>>>(q, k, v, w16,
                                           wq_b, wk_b, wv_b,
                                           q16, k16, v16, QSCALE);

    dim3 ablk(256), agrid(SEQ/128, NH, NB);
    attn_mma_kernel<<<agrid, ablk, ASMEM_BYTES>>>(q16, k16, v16, c16);

    dim3 ogrid(DM/128, MROWS/128);
    gemm_out<<<ogrid, gblk, GSMEM_BYTES>>>(c16, w16 + 3*WSZ, wo_b, out);
}